// round 14
// baseline (speedup 1.0000x reference)
#include <cuda_runtime.h>
#include <cuda_fp16.h>
#include <math.h>
#include <stdint.h>

// Problem constants
#define BB 2
#define TT 2048
#define DIM 2048
#define NH 16
#define NKV 4
#define NREP 4
#define ROPE_D 64
#define NOPE_D 128
#define V_D 128
#define QK_D 192
#define KV_RANK 512
#define Q_RANK 1536
#define MROWS (BB*TT)   // 4096

// fused widths
#define N_DOWN 2048            // [kv_c(512) | q_c(1536)]
#define N_KVUP 1280            // [k_nope(512) | k_rope(256) | v(512)]
#define N_QUP  3072            // [q_nope(2048) | q_rope(1024)]
#define VOFF   (NKV*NOPE_D + NKV*ROPE_D)   // 768

// ------------------------- scratch (static device memory) -------------------
__device__ __half g_w_down[N_DOWN * DIM];       // transposed [N][K], fp16
__device__ __half g_w_kv  [N_KVUP * KV_RANK];
__device__ __half g_w_q   [N_QUP * Q_RANK];
__device__ __half g_w_o   [DIM * (NH*V_D)];
__device__ __half g_x_r   [MROWS * DIM];
__device__ __half g_cdown [MROWS * N_DOWN];
__device__ __half g_kvup  [MROWS * N_KVUP];
__device__ __half g_qup   [MROWS * N_QUP];
__device__ __half g_qcat  [BB*NH  * TT * QK_D];
__device__ __half g_kcat  [BB*NKV * TT * QK_D];
__device__ __half g_vt    [BB*NKV * V_D * TT];
__device__ __half g_attn  [MROWS * (NH*V_D)];
__device__ float  g_ropec [TT * ROPE_D];
__device__ float  g_ropes [TT * ROPE_D];

// ------------------------- common PTX helpers -------------------------------
__device__ __forceinline__ uint32_t s2u(const void* p) {
    return (uint32_t)__cvta_generic_to_shared(p);
}
__device__ __forceinline__ void cp_async16(void* smem, const void* gmem) {
    asm volatile("cp.async.cg.shared.global [%0], [%1], 16;\n"
                 :: "r"(s2u(smem)), "l"(gmem));
}
__device__ __forceinline__ void cp_commit() {
    asm volatile("cp.async.commit_group;\n" ::: "memory");
}
template<int N>
__device__ __forceinline__ void cp_wait() {
    asm volatile("cp.async.wait_group %0;\n" :: "n"(N) : "memory");
}

#define LDMX4(r0, r1, r2, r3, addr) \
    asm volatile("ldmatrix.sync.aligned.m8n8.x4.shared.b16 {%0,%1,%2,%3}, [%4];" \
                 : "=r"(r0), "=r"(r1), "=r"(r2), "=r"(r3) : "r"(addr))

#define MMA_F16(c, a, b) \
    asm volatile("mma.sync.aligned.m16n8k16.row.col.f32.f16.f16.f32 " \
                 "{%0,%1,%2,%3},{%4,%5,%6,%7},{%8,%9},{%0,%1,%2,%3};" \
                 : "+f"((c)[0]), "+f"((c)[1]), "+f"((c)[2]), "+f"((c)[3]) \
                 : "r"((a)[0]), "r"((a)[1]), "r"((a)[2]), "r"((a)[3]), \
                   "r"((b)[0]), "r"((b)[1]))

// ------------------------- prep kernels --------------------------------------
__global__ void copy_half4(__half2* __restrict__ dst, const float4* __restrict__ src,
                           int total4)
{
    for (int i = blockIdx.x * blockDim.x + threadIdx.x; i < total4;
         i += gridDim.x * blockDim.x) {
        float4 v = src[i];
        dst[2*i]   = __floats2half2_rn(v.x, v.y);
        dst[2*i+1] = __floats2half2_rn(v.z, v.w);
    }
}

// merged transpose+convert: 8 jobs in one launch
struct TJobs {
    const float* src[8];
    __half* dst[8];
    int R[8], C[8], noff[8], start[8];
    int njobs;
};

__global__ void trans_half_multi(TJobs jobs)
{
    __shared__ float tile[32][33];
    const int bid = blockIdx.x;
    int jj = 0;
    #pragma unroll
    for (int k = 1; k < 8; k++)
        if (k < jobs.njobs && bid >= jobs.start[k]) jj = k;
    const int local = bid - jobs.start[jj];
    const int C = jobs.C[jj], R = jobs.R[jj], noff = jobs.noff[jj];
    const int tx = C >> 5;
    const int c0 = (local % tx) * 32;
    const int r0 = (local / tx) * 32;
    const float* src = jobs.src[jj];
    __half* dst = jobs.dst[jj];

    for (int i = threadIdx.y; i < 32; i += 8)
        tile[i][threadIdx.x] = src[(size_t)(r0 + i) * C + c0 + threadIdx.x];
    __syncthreads();
    for (int i = threadIdx.y; i < 32; i += 8)
        dst[(size_t)(noff + c0 + i) * R + r0 + threadIdx.x] =
            __float2half_rn(tile[threadIdx.x][i]);
}

// rope cos/sin table: [t][dr], dr in [0,64)
__global__ void rope_table(float* __restrict__ rc, float* __restrict__ rs)
{
    int idx = blockIdx.x * blockDim.x + threadIdx.x;
    if (idx >= TT * ROPE_D) return;
    int t = idx >> 6, dr = idx & 63;
    int j = dr & 31;
    float theta = exp2f(-0.4152410118609203f * (float)j);  // 10000^(-j/32)
    float ang = (float)t * theta;
    rc[idx] = cosf(ang);
    rs[idx] = sinf(ang);
}

// ---- fused assembly: assemble_q | assemble_k | trans_v in one launch --------
#define NQB ((BB*NH*TT*QK_D + 255) / 256)
#define NKB ((BB*NKV*TT*QK_D + 255) / 256)
#define NVB ((512/32) * (MROWS/32))

__global__ void assemble_all(const __half* __restrict__ qup,
                             const __half* __restrict__ kvup,
                             const float* __restrict__ rc,
                             const float* __restrict__ rs,
                             __half* __restrict__ qcat,
                             __half* __restrict__ kcat,
                             __half* __restrict__ vt)
{
    __shared__ float tile[32][33];
    const int bid = blockIdx.x;

    if (bid < NQB) {
        size_t idx = (size_t)bid * 256 + threadIdx.x;
        int d = (int)(idx % QK_D);
        size_t rem = idx / QK_D;
        int t = (int)(rem % TT); rem /= TT;
        int h = (int)(rem % NH);
        int b = (int)(rem / NH);
        size_t row = (size_t)b * TT + t;
        const float scale = rsqrtf((float)QK_D);
        float val;
        if (d < NOPE_D) {
            val = __half2float(qup[row * N_QUP + h * NOPE_D + d]);
        } else {
            int dr = d - NOPE_D;
            size_t ro = row * N_QUP + NH*NOPE_D + h * ROPE_D;
            float x0  = __half2float(qup[ro + dr]);
            float rot = (dr < 32) ? -__half2float(qup[ro + dr + 32])
                                  :  __half2float(qup[ro + dr - 32]);
            val = x0 * rc[t * ROPE_D + dr] + rot * rs[t * ROPE_D + dr];
        }
        qcat[idx] = __float2half_rn(val * scale);
    } else if (bid < NQB + NKB) {
        size_t idx = (size_t)(bid - NQB) * 256 + threadIdx.x;
        int d = (int)(idx % QK_D);
        size_t rem = idx / QK_D;
        int t = (int)(rem % TT); rem /= TT;
        int h = (int)(rem % NKV);
        int b = (int)(rem / NKV);
        size_t row = (size_t)b * TT + t;
        float val;
        if (d < NOPE_D) {
            val = __half2float(kvup[row * N_KVUP + h * NOPE_D + d]);
        } else {
            int dr = d - NOPE_D;
            size_t ro = row * N_KVUP + NKV*NOPE_D + h * ROPE_D;
            float x0  = __half2float(kvup[ro + dr]);
            float rot = (dr < 32) ? -__half2float(kvup[ro + dr + 32])
                                  :  __half2float(kvup[ro + dr - 32]);
            val = x0 * rc[t * ROPE_D + dr] + rot * rs[t * ROPE_D + dr];
        }
        kcat[idx] = __float2half_rn(val);
    } else {
        const int vb = bid - NQB - NKB;
        const int tx = threadIdx.x & 31;
        const int ty = threadIdx.x >> 5;
        const int c0 = (vb % (512/32)) * 32;
        const int r0 = (vb / (512/32)) * 32;
        for (int i = ty; i < 32; i += 8)
            tile[i][tx] =
                __half2float(kvup[(size_t)(r0 + i) * N_KVUP + VOFF + c0 + tx]);
        __syncthreads();
        const int b = r0 >> 11;
        for (int i = ty; i < 32; i += 8)
            vt[(size_t)(b * 512 + c0 + i) * TT + (r0 & 2047) + tx] =
                __float2half_rn(tile[tx][i]);
    }
}

// ------------------------- fp16 tensor-core GEMM (mma.sync) -----------------
// R11 configuration (measured plateau): block 128x128, 8 warps of 64x32,
// 256 threads, 3-stage cp.async ring, 2 CTAs/SM, K-chunk = 32 halfs.
#define LDH 40                              // half pitch (80 B/row)
#define TSH (128*LDH)                       // halfs per operand per stage
#define GST3 3
#define GH_SMEM (GST3 * 2 * TSH * sizeof(__half))   // 61440 B

__global__ __launch_bounds__(256, 2) void gemm_f16(
    const __half* __restrict__ A, int lda,
    const __half* __restrict__ Bt,
    void* __restrict__ Cp, int N, int K, int c_half)
{
    extern __shared__ __half smh[];

    const int tid  = threadIdx.x;
    const int lane = tid & 31;
    const int wid  = tid >> 5;
    const int bx = blockIdx.x, by = blockIdx.y;

    const int m0 = (wid & 1) * 64;
    const int n0 = (wid >> 1) * 32;

    const int rselA = ((lane >> 3) & 1) * 8 + (lane & 7);
    const int cselA = (lane >> 4) * 8;              // halfs
    const int rselB = ((lane >> 4) & 1) * 8 + (lane & 7);
    const int cselB = ((lane >> 3) & 1) * 8;        // halfs

    const int l_row = tid >> 1;
    const int l_col = (tid & 1) * 16;               // halfs (32 B)

    const __half* Agb = A  + (size_t)(by * 128 + l_row) * lda + l_col;
    const __half* Bgb = Bt + (size_t)(bx * 128 + l_row) * K   + l_col;

    float acc[4][4][4];
    #pragma unroll
    for (int i = 0; i < 4; i++)
        #pragma unroll
        for (int j = 0; j < 4; j++)
            #pragma unroll
            for (int r = 0; r < 4; r++) acc[i][j][r] = 0.f;

    const int nch = K >> 5;

    // prologue: stages 0,1
    #pragma unroll
    for (int p = 0; p < 2; p++) {
        __half* Asb = smh + p * 2 * TSH + l_row * LDH + l_col;
        __half* Bsb = Asb + TSH;
        const __half* Ag = Agb + p * 32;
        const __half* Bg = Bgb + p * 32;
        #pragma unroll
        for (int i = 0; i < 2; i++) cp_async16(Asb + i*8, Ag + i*8);
        #pragma unroll
        for (int i = 0; i < 2; i++) cp_async16(Bsb + i*8, Bg + i*8);
        cp_commit();
    }

    int s = 0, s2 = 2;
    for (int ch = 0; ch < nch; ch++) {
        cp_wait<1>();
        __syncthreads();

        if (ch + 2 < nch) {
            const int k0 = (ch + 2) << 5;
            __half* Asb = smh + s2 * 2 * TSH + l_row * LDH + l_col;
            __half* Bsb = Asb + TSH;
            const __half* Ag = Agb + k0;
            const __half* Bg = Bgb + k0;
            #pragma unroll
            for (int i = 0; i < 2; i++) cp_async16(Asb + i*8, Ag + i*8);
            #pragma unroll
            for (int i = 0; i < 2; i++) cp_async16(Bsb + i*8, Bg + i*8);
        }
        cp_commit();

        const __half* Asb = smh + s * 2 * TSH;
        const __half* Bsb = Asb + TSH;

        #pragma unroll
        for (int kk = 0; kk < 2; kk++) {
            uint32_t af[4][4], bf[4][2];
            #pragma unroll
            for (int mi = 0; mi < 4; mi++) {
                LDMX4(af[mi][0], af[mi][1], af[mi][2], af[mi][3],
                      s2u(Asb + (m0 + mi*16 + rselA) * LDH + kk*16 + cselA));
            }
            #pragma unroll
            for (int nip = 0; nip < 2; nip++) {
                LDMX4(bf[2*nip][0], bf[2*nip][1], bf[2*nip+1][0], bf[2*nip+1][1],
                      s2u(Bsb + (n0 + nip*16 + rselB) * LDH + kk*16 + cselB));
            }
            #pragma unroll
            for (int mi = 0; mi < 4; mi++)
                #pragma unroll
                for (int ni = 0; ni < 4; ni++)
                    MMA_F16(acc[mi][ni], af[mi], bf[ni]);
        }
        s  = (s  == GST3-1) ? 0 : s  + 1;
        s2 = (s2 == GST3-1) ? 0 : s2 + 1;
    }

    const int crow = by * 128 + m0 + (lane >> 2);
    const int ccol = bx * 128 + n0 + (lane & 3) * 2;
    if (c_half) {
        __half* C = (__half*)Cp;
        #pragma unroll
        for (int mi = 0; mi < 4; mi++) {
            #pragma unroll
            for (int ni = 0; ni < 4; ni++) {
                const int r = crow + mi * 16;
                const int c = ccol + ni * 8;
                *(__half2*)(C + (size_t)r * N + c) =
                    __floats2half2_rn(acc[mi][ni][0], acc[mi][ni][1]);
                *(__half2*)(C + (size_t)(r + 8) * N + c) =
                    __floats2half2_rn(acc[mi][ni][2], acc[mi][ni][3]);
            }
        }
    } else {
        float* C = (float*)Cp;
        #pragma unroll
        for (int mi = 0; mi < 4; mi++) {
            #pragma unroll
            for (int ni = 0; ni < 4; ni++) {
                const int r = crow + mi * 16;
                const int c = ccol + ni * 8;
                *(float2*)(C + (size_t)r * N + c) =
                    make_float2(acc[mi][ni][0], acc[mi][ni][1]);
                *(float2*)(C + (size_t)(r + 8) * N + c) =
                    make_float2(acc[mi][ni][2], acc[mi][ni][3]);
            }
        }
    }
}

// ------------------------- flash attention (fp16 mma, K-tile 128) -----------
// Q-tile 128 x K-tile 128. Single-buffered pipeline: K_{jt+1} issued during
// PV_jt, V_{jt+1} issued after end-of-iter barrier (lands during S_{jt+1}).
#define LQH 200
#define LKH 200
#define LVTH 136
#define LPH 136
#define QS_SZ (128*LQH)
#define KS_SZ (128*LKH)
#define VTS_SZ (128*LVTH)
#define PS_SZ (128*LPH)
#define ATTN_SMEM ((QS_SZ + KS_SZ + VTS_SZ + PS_SZ) * sizeof(__half))

__global__ __launch_bounds__(256) void flash_attn_mma(
    const __half* __restrict__ q, const __half* __restrict__ k,
    const __half* __restrict__ vt, __half* __restrict__ out)
{
    extern __shared__ __half sh[];
    __half* Qs  = sh;
    __half* Ks  = sh + QS_SZ;
    __half* Vts = Ks + KS_SZ;
    __half* Ps  = Vts + VTS_SZ;

    const int bid  = blockIdx.x;
    const int qi   = (TT/128 - 1) - (bid >> 5);   // big tiles scheduled first
    const int head = bid & 31;
    const int b = head / NH, h = head % NH;
    const int hkv = h / NREP;
    const int tid = threadIdx.x;
    const int lane = tid & 31, wid = tid >> 5;
    const int r = lane >> 2, t = lane & 3;
    const int qw = wid * 16;
    const int qrow0 = qi * 128;

    const int rselA = ((lane >> 3) & 1) * 8 + (lane & 7);
    const int cselA = (lane >> 4) * 8;
    const int rselB = ((lane >> 4) & 1) * 8 + (lane & 7);
    const int cselB = ((lane >> 3) & 1) * 8;

    const __half* qbase = q + ((size_t)head * TT + qrow0) * QK_D;
    const __half* kbase = k + ((size_t)(b * NKV + hkv) * TT) * QK_D;
    const __half* vtbase = vt + (size_t)(b * 512 + hkv * 128) * TT;

    // prefetch: Q (group), K0 (group), V0 (group). 16B = 8 halfs per cp.
    for (int i = tid; i < 128 * 24; i += 256) {
        int rr = i / 24, c8 = i % 24;
        cp_async16(Qs + rr * LQH + c8 * 8, qbase + (size_t)rr * QK_D + c8 * 8);
    }
    cp_commit();
    for (int i = tid; i < 128 * 24; i += 256) {
        int rr = i / 24, c8 = i % 24;
        cp_async16(Ks + rr * LKH + c8 * 8, kbase + (size_t)rr * QK_D + c8 * 8);
    }
    cp_commit();
    for (int i = tid; i < 128 * 16; i += 256) {
        int rr = i >> 4, c8 = i & 15;
        cp_async16(Vts + rr * LVTH + c8 * 8, vtbase + (size_t)rr * TT + c8 * 8);
    }
    cp_commit();

    float m0 = -1e30f, m1 = -1e30f, l0 = 0.f, l1 = 0.f;
    float oacc[16][4];
    #pragma unroll
    for (int j = 0; j < 16; j++)
        #pragma unroll
        for (int c = 0; c < 4; c++) oacc[j][c] = 0.f;

    const int niter = qi + 1;
    for (int jt = 0; jt < niter; jt++) {
        const int krow0 = jt * 128;

        cp_wait<1>();          // Q + K_jt complete (V_jt may be in flight)
        __syncthreads();

        // ---- S = Q @ K^T  (16 x 128 per warp) ----
        float sacc[16][4];
        #pragma unroll
        for (int j = 0; j < 16; j++)
            #pragma unroll
            for (int c = 0; c < 4; c++) sacc[j][c] = 0.f;

        #pragma unroll 2
        for (int kc = 0; kc < 12; kc++) {
            uint32_t a[4];
            LDMX4(a[0], a[1], a[2], a[3],
                  s2u(Qs + (qw + rselA) * LQH + kc*16 + cselA));
            #pragma unroll
            for (int jp = 0; jp < 8; jp++) {
                uint32_t b0[2], b1[2];
                LDMX4(b0[0], b0[1], b1[0], b1[1],
                      s2u(Ks + (jp*16 + rselB) * LKH + kc*16 + cselB));
                MMA_F16(sacc[2*jp],   a, b0);
                MMA_F16(sacc[2*jp+1], a, b1);
            }
        }

        // ---- mask + online softmax (128 cols) ----
        const int gr0 = qrow0 + qw + r;
        const bool need_mask = (jt == qi);
        float mx0 = m0, mx1 = m1;
        #pragma unroll
        for (int j = 0; j < 16; j++) {
            if (need_mask) {
                int gc = krow0 + 8 * j + 2 * t;
                if (gc     > gr0)     sacc[j][0] = -1e30f;
                if (gc + 1 > gr0)     sacc[j][1] = -1e30f;
                if (gc     > gr0 + 8) sacc[j][2] = -1e30f;
                if (gc + 1 > gr0 + 8) sacc[j][3] = -1e30f;
            }
            mx0 = fmaxf(mx0, fmaxf(sacc[j][0], sacc[j][1]));
            mx1 = fmaxf(mx1, fmaxf(sacc[j][2], sacc[j][3]));
        }
        mx0 = fmaxf(mx0, __shfl_xor_sync(0xffffffffu, mx0, 1));
        mx0 = fmaxf(mx0, __shfl_xor_sync(0xffffffffu, mx0, 2));
        mx1 = fmaxf(mx1, __shfl_xor_sync(0xffffffffu, mx1, 1));
        mx1 = fmaxf(mx1, __shfl_xor_sync(0xffffffffu, mx1, 2));

        float alpha0 = __expf(m0 - mx0);
        float alpha1 = __expf(m1 - mx1);
        m0 = mx0; m1 = mx1;

        float ls0 = 0.f, ls1 = 0.f;
        __half2* pp = (__half2*)(Ps + (qw + r) * LPH);
        #pragma unroll
        for (int j = 0; j < 16; j++) {
            float p0 = __expf(sacc[j][0] - mx0);
            float p1 = __expf(sacc[j][1] - mx0);
            float p2 = __expf(sacc[j][2] - mx1);
            float p3 = __expf(sacc[j][3] - mx1);
            ls0 += p0 + p1; ls1 += p2 + p3;
            pp[4*j + t]                = __floats2half2_rn(p0, p1);
            pp[8*(LPH/2) + 4*j + t]    = __floats2half2_rn(p2, p3);
        }
        ls0 += __shfl_xor_sync(0xffffffffu, ls0, 1);
        ls0 += __shfl_xor_sync(0xffffffffu, ls0, 2);
        ls1 += __shfl_xor_sync(0xffffffffu, ls1, 1);
        ls1 += __shfl_xor_sync(0xffffffffu, ls1, 2);
        l0 = l0 * alpha0 + ls0;
        l1 = l1 * alpha1 + ls1;

        #pragma unroll
        for (int j = 0; j < 16; j++) {
            oacc[j][0] *= alpha0; oacc[j][1] *= alpha0;
            oacc[j][2] *= alpha1; oacc[j][3] *= alpha1;
        }

        cp_wait<0>();          // V_jt complete; all threads done reading Ks
        __syncthreads();

        // issue K_{jt+1} now — PV does not touch Ks
        if (jt + 1 < niter) {
            const int kn0 = (jt + 1) * 128;
            for (int i = tid; i < 128 * 24; i += 256) {
                int rr = i / 24, c8 = i % 24;
                cp_async16(Ks + rr * LKH + c8 * 8,
                           kbase + (size_t)(kn0 + rr) * QK_D + c8 * 8);
            }
            cp_commit();
        }

        // ---- O += P @ V  (P: 16x128, Vt: 128d x 128t) ----
        #pragma unroll
        for (int kc = 0; kc < 8; kc++) {
            uint32_t a[4];
            LDMX4(a[0], a[1], a[2], a[3],
                  s2u(Ps + (qw + rselA) * LPH + kc*16 + cselA));
            #pragma unroll
            for (int jp = 0; jp < 8; jp++) {
                uint32_t b0[2], b1[2];
                LDMX4(b0[0], b0[1], b1[0], b1[1],
                      s2u(Vts + (jp*16 + rselB) * LVTH + kc*16 + cselB));
                MMA_F16(oacc[2*jp],   a, b0);
                MMA_F16(oacc[2*jp+1], a, b1);
            }
        }
        __syncthreads();       // all threads done reading Vts/Ps

        // issue V_{jt+1} — lands during S_{jt+1}
        if (jt + 1 < niter) {
            const int kn0 = (jt + 1) * 128;
            for (int i = tid; i < 128 * 16; i += 256) {
                int rr = i >> 4, c8 = i & 15;
                cp_async16(Vts + rr * LVTH + c8 * 8,
                           vtbase + (size_t)rr * TT + kn0 + c8 * 8);
            }
            cp_commit();
        }
    }

    const float inv0 = 1.0f / l0;
    const float inv1 = 1.0f / l1;
    const int gr0 = qrow0 + qw + r;
    __half* ob = out + ((size_t)b * TT + gr0) * (NH * V_D) + h * V_D;
    #pragma unroll
    for (int j = 0; j < 16; j++) {
        int c = 8 * j + 2 * t;
        *(__half2*)(ob + c) =
            __floats2half2_rn(oacc[j][0] * inv0, oacc[j][1] * inv0);
        *(__half2*)(ob + (size_t)8 * (NH * V_D) + c) =
            __floats2half2_rn(oacc[j][2] * inv1, oacc[j][3] * inv1);
    }
}

// ------------------------- launch -------------------------------------------
extern "C" void kernel_launch(void* const* d_in, const int* in_sizes, int n_in,
                              void* d_out, int out_size)
{
    const float* x         = (const float*)d_in[0];
    const float* W_kv_down = (const float*)d_in[1];
    const float* W_k_nope  = (const float*)d_in[2];
    const float* W_k_rope  = (const float*)d_in[3];
    const float* W_v       = (const float*)d_in[4];
    const float* W_q_down  = (const float*)d_in[5];
    const float* W_q_nope  = (const float*)d_in[6];
    const float* W_q_rope  = (const float*)d_in[7];
    const float* W_o       = (const float*)d_in[8];
    float* out = (float*)d_out;

    __half *w_down, *w_kv, *w_q, *w_o, *x_r, *cdown, *kvup, *qup;
    __half *qcat, *kcat, *vt, *attn;
    float *rc, *rs;
    cudaGetSymbolAddress((void**)&w_down, g_w_down);
    cudaGetSymbolAddress((void**)&w_kv,   g_w_kv);
    cudaGetSymbolAddress((void**)&w_q,    g_w_q);
    cudaGetSymbolAddress((void**)&w_o,    g_w_o);
    cudaGetSymbolAddress((void**)&x_r,    g_x_r);
    cudaGetSymbolAddress((void**)&cdown,  g_cdown);
    cudaGetSymbolAddress((void**)&kvup,   g_kvup);
    cudaGetSymbolAddress((void**)&qup,    g_qup);
    cudaGetSymbolAddress((void**)&qcat,   g_qcat);
    cudaGetSymbolAddress((void**)&kcat,   g_kcat);
    cudaGetSymbolAddress((void**)&vt,     g_vt);
    cudaGetSymbolAddress((void**)&attn,   g_attn);
    cudaGetSymbolAddress((void**)&rc,     g_ropec);
    cudaGetSymbolAddress((void**)&rs,     g_ropes);

    cudaFuncSetAttribute(gemm_f16, cudaFuncAttributeMaxDynamicSharedMemorySize,
                         (int)GH_SMEM);
    cudaFuncSetAttribute(flash_attn_mma, cudaFuncAttributeMaxDynamicSharedMemorySize,
                         (int)ATTN_SMEM);

    // ---- merged weight transpose+convert (single launch) ----
    {
        TJobs jobs;
        const float* srcs[8] = {W_kv_down, W_q_down, W_k_nope, W_k_rope,
                                W_v, W_q_nope, W_q_rope, W_o};
        __half* dsts[8] = {w_down, w_down, w_kv, w_kv, w_kv, w_q, w_q, w_o};
        int Rs[8]    = {DIM, DIM, KV_RANK, KV_RANK, KV_RANK, Q_RANK, Q_RANK, NH*V_D};
        int Cs[8]    = {KV_RANK, Q_RANK, NKV*NOPE_D, NKV*ROPE_D, NKV*V_D,
                        NH*NOPE_D, NH*ROPE_D, DIM};
        int noffs[8] = {0, KV_RANK, 0, NKV*NOPE_D, VOFF, 0, NH*NOPE_D, 0};
        int cum = 0;
        for (int k = 0; k < 8; k++) {
            jobs.src[k] = srcs[k]; jobs.dst[k] = dsts[k];
            jobs.R[k] = Rs[k]; jobs.C[k] = Cs[k]; jobs.noff[k] = noffs[k];
            jobs.start[k] = cum;
            cum += (Rs[k] / 32) * (Cs[k] / 32);
        }
        jobs.njobs = 8;
        trans_half_multi<<<cum, dim3(32, 8)>>>(jobs);
    }
    copy_half4<<<592, 256>>>((__half2*)x_r, (const float4*)x, MROWS * DIM / 4);
    rope_table<<<(TT * ROPE_D + 255) / 256, 256>>>(rc, rs);

    // ---- fused down projection: [kv_c | q_c] ----
    gemm_f16<<<dim3(N_DOWN/128, MROWS/128), 256, GH_SMEM>>>(
        x_r, DIM, w_down, cdown, N_DOWN, DIM, 1);

    // ---- fused up projections ----
    gemm_f16<<<dim3(N_KVUP/128, MROWS/128), 256, GH_SMEM>>>(
        cdown, N_DOWN, w_kv, kvup, N_KVUP, KV_RANK, 1);
    gemm_f16<<<dim3(N_QUP/128, MROWS/128), 256, GH_SMEM>>>(
        cdown + KV_RANK, N_DOWN, w_q, qup, N_QUP, Q_RANK, 1);

    // ---- fused RoPE assembly + V transpose (single launch) ----
    assemble_all<<<NQB + NKB + NVB, 256>>>(qup, kvup, rc, rs, qcat, kcat, vt);

    // ---- attention (1D grid, largest tiles first) ----
    flash_attn_mma<<<(TT/128) * BB * NH, 256, ATTN_SMEM>>>(qcat, kcat, vt, attn);

    // ---- output projection (float out) ----
    gemm_f16<<<dim3(DIM/128, MROWS/128), 256, GH_SMEM>>>(
        attn, NH*V_D, w_o, out, DIM, NH*V_D, 0);
}

// round 15
// speedup vs baseline: 1.0598x; 1.0598x over previous
#include <cuda_runtime.h>
#include <cuda_fp16.h>
#include <math.h>
#include <stdint.h>

// Problem constants
#define BB 2
#define TT 2048
#define DIM 2048
#define NH 16
#define NKV 4
#define NREP 4
#define ROPE_D 64
#define NOPE_D 128
#define V_D 128
#define QK_D 192
#define KV_RANK 512
#define Q_RANK 1536
#define MROWS (BB*TT)   // 4096

// fused widths
#define N_DOWN 2048            // [kv_c(512) | q_c(1536)]
#define N_KVUP 1280            // [k_nope(512) | k_rope(256) | v(512)]
#define N_QUP  3072            // [q_nope(2048) | q_rope(1024)]
#define VOFF   (NKV*NOPE_D + NKV*ROPE_D)   // 768

// ------------------------- scratch (static device memory) -------------------
__device__ __half g_w_down[N_DOWN * DIM];       // transposed [N][K], fp16
__device__ __half g_w_kv  [N_KVUP * KV_RANK];
__device__ __half g_w_q   [N_QUP * Q_RANK];
__device__ __half g_w_o   [DIM * (NH*V_D)];
__device__ __half g_x_r   [MROWS * DIM];
__device__ __half g_cdown [MROWS * N_DOWN];
__device__ __half g_kvup  [MROWS * N_KVUP];
__device__ __half g_qup   [MROWS * N_QUP];
__device__ __half g_qcat  [BB*NH  * TT * QK_D];
__device__ __half g_kcat  [BB*NKV * TT * QK_D];
__device__ __half g_vt    [BB*NKV * V_D * TT];
__device__ __half g_attn  [MROWS * (NH*V_D)];
__device__ float  g_ropec [TT * ROPE_D];
__device__ float  g_ropes [TT * ROPE_D];

// ------------------------- common PTX helpers -------------------------------
__device__ __forceinline__ uint32_t s2u(const void* p) {
    return (uint32_t)__cvta_generic_to_shared(p);
}
__device__ __forceinline__ void cp_async16(void* smem, const void* gmem) {
    asm volatile("cp.async.cg.shared.global [%0], [%1], 16;\n"
                 :: "r"(s2u(smem)), "l"(gmem));
}
__device__ __forceinline__ void cp_commit() {
    asm volatile("cp.async.commit_group;\n" ::: "memory");
}
template<int N>
__device__ __forceinline__ void cp_wait() {
    asm volatile("cp.async.wait_group %0;\n" :: "n"(N) : "memory");
}

#define LDMX4(r0, r1, r2, r3, addr) \
    asm volatile("ldmatrix.sync.aligned.m8n8.x4.shared.b16 {%0,%1,%2,%3}, [%4];" \
                 : "=r"(r0), "=r"(r1), "=r"(r2), "=r"(r3) : "r"(addr))

#define MMA_F16(c, a, b) \
    asm volatile("mma.sync.aligned.m16n8k16.row.col.f32.f16.f16.f32 " \
                 "{%0,%1,%2,%3},{%4,%5,%6,%7},{%8,%9},{%0,%1,%2,%3};" \
                 : "+f"((c)[0]), "+f"((c)[1]), "+f"((c)[2]), "+f"((c)[3]) \
                 : "r"((a)[0]), "r"((a)[1]), "r"((a)[2]), "r"((a)[3]), \
                   "r"((b)[0]), "r"((b)[1]))

// ------------------------- prep kernels --------------------------------------
__global__ void copy_half4(__half2* __restrict__ dst, const float4* __restrict__ src,
                           int total4)
{
    for (int i = blockIdx.x * blockDim.x + threadIdx.x; i < total4;
         i += gridDim.x * blockDim.x) {
        float4 v = src[i];
        dst[2*i]   = __floats2half2_rn(v.x, v.y);
        dst[2*i+1] = __floats2half2_rn(v.z, v.w);
    }
}

// merged transpose+convert: 8 jobs in one launch
struct TJobs {
    const float* src[8];
    __half* dst[8];
    int R[8], C[8], noff[8], start[8];
    int njobs;
};

__global__ void trans_half_multi(TJobs jobs)
{
    __shared__ float tile[32][33];
    const int bid = blockIdx.x;
    int jj = 0;
    #pragma unroll
    for (int k = 1; k < 8; k++)
        if (k < jobs.njobs && bid >= jobs.start[k]) jj = k;
    const int local = bid - jobs.start[jj];
    const int C = jobs.C[jj], R = jobs.R[jj], noff = jobs.noff[jj];
    const int tx = C >> 5;
    const int c0 = (local % tx) * 32;
    const int r0 = (local / tx) * 32;
    const float* src = jobs.src[jj];
    __half* dst = jobs.dst[jj];

    for (int i = threadIdx.y; i < 32; i += 8)
        tile[i][threadIdx.x] = src[(size_t)(r0 + i) * C + c0 + threadIdx.x];
    __syncthreads();
    for (int i = threadIdx.y; i < 32; i += 8)
        dst[(size_t)(noff + c0 + i) * R + r0 + threadIdx.x] =
            __float2half_rn(tile[threadIdx.x][i]);
}

// rope cos/sin table: [t][dr], dr in [0,64)
__global__ void rope_table(float* __restrict__ rc, float* __restrict__ rs)
{
    int idx = blockIdx.x * blockDim.x + threadIdx.x;
    if (idx >= TT * ROPE_D) return;
    int t = idx >> 6, dr = idx & 63;
    int j = dr & 31;
    float theta = exp2f(-0.4152410118609203f * (float)j);  // 10000^(-j/32)
    float ang = (float)t * theta;
    rc[idx] = cosf(ang);
    rs[idx] = sinf(ang);
}

// ---- fused assembly (vectorized, div/mod-free) ------------------------------
// Block ranges: q-nope | q-rope | k-nope | k-rope | trans_v.
// Row id enumerates (b,h,t) with pure shifts (all dims powers of 2).
#define NQN (BB*NH*TT*16/256)    // 4096  (16 uint4 segs per 128-col row)
#define NQR (BB*NH*TT*8/256)     // 2048  (8 uint4 segs per 64-col row)
#define NKN (BB*NKV*TT*16/256)   // 1024
#define NKR (BB*NKV*TT*8/256)    // 512
#define NTV ((512/32) * (MROWS/32))   // 2048

__global__ void assemble_all(const __half* __restrict__ qup,
                             const __half* __restrict__ kvup,
                             const float* __restrict__ rc,
                             const float* __restrict__ rs,
                             __half* __restrict__ qcat,
                             __half* __restrict__ kcat,
                             __half* __restrict__ vt)
{
    __shared__ float tile[32][33];
    const int bid = blockIdx.x;
    const int tid = threadIdx.x;
    const float scale = rsqrtf((float)QK_D);

    if (bid < NQN) {
        // q nope: row = (b*NH+h)*TT + t; copy 8 halfs * scale
        int gid = bid * 256 + tid;
        int row = gid >> 4, seg = gid & 15;
        int h = (row >> 11) & 15, t = row & 2047, b = row >> 15;
        uint4 v = *(const uint4*)(qup + (size_t)(b * TT + t) * N_QUP
                                  + h * NOPE_D + seg * 8);
        __half2* hv = (__half2*)&v;
        #pragma unroll
        for (int i = 0; i < 4; i++) {
            float2 f = __half22float2(hv[i]);
            hv[i] = __floats2half2_rn(f.x * scale, f.y * scale);
        }
        *(uint4*)(qcat + (size_t)row * QK_D + seg * 8) = v;
    } else if (bid < NQN + NQR) {
        // q rope
        int gid = (bid - NQN) * 256 + tid;
        int row = gid >> 3, part = gid & 7;
        int h = (row >> 11) & 15, t = row & 2047, b = row >> 15;
        int dr0 = part * 8;
        const __half* base = qup + (size_t)(b * TT + t) * N_QUP
                             + NH * NOPE_D + h * ROPE_D;
        uint4 xv = *(const uint4*)(base + dr0);
        uint4 rv = *(const uint4*)(base + ((part < 4) ? dr0 + 32 : dr0 - 32));
        const float sgn = (part < 4) ? -1.f : 1.f;
        const float* rcp = rc + t * ROPE_D + dr0;
        const float* rsp = rs + t * ROPE_D + dr0;
        const __half* xh = (const __half*)&xv;
        const __half* rh = (const __half*)&rv;
        __half out8[8];
        #pragma unroll
        for (int i = 0; i < 8; i++) {
            float val = __half2float(xh[i]) * rcp[i]
                      + sgn * __half2float(rh[i]) * rsp[i];
            out8[i] = __float2half_rn(val * scale);
        }
        *(uint4*)(qcat + (size_t)row * QK_D + NOPE_D + dr0) = *(uint4*)out8;
    } else if (bid < NQN + NQR + NKN) {
        // k nope: row = (b*NKV+h)*TT + t
        int gid = (bid - NQN - NQR) * 256 + tid;
        int row = gid >> 4, seg = gid & 15;
        int h = (row >> 11) & 3, t = row & 2047, b = row >> 13;
        uint4 v = *(const uint4*)(kvup + (size_t)(b * TT + t) * N_KVUP
                                  + h * NOPE_D + seg * 8);
        *(uint4*)(kcat + (size_t)row * QK_D + seg * 8) = v;
    } else if (bid < NQN + NQR + NKN + NKR) {
        // k rope
        int gid = (bid - NQN - NQR - NKN) * 256 + tid;
        int row = gid >> 3, part = gid & 7;
        int h = (row >> 11) & 3, t = row & 2047, b = row >> 13;
        int dr0 = part * 8;
        const __half* base = kvup + (size_t)(b * TT + t) * N_KVUP
                             + NKV * NOPE_D + h * ROPE_D;
        uint4 xv = *(const uint4*)(base + dr0);
        uint4 rv = *(const uint4*)(base + ((part < 4) ? dr0 + 32 : dr0 - 32));
        const float sgn = (part < 4) ? -1.f : 1.f;
        const float* rcp = rc + t * ROPE_D + dr0;
        const float* rsp = rs + t * ROPE_D + dr0;
        const __half* xh = (const __half*)&xv;
        const __half* rh = (const __half*)&rv;
        __half out8[8];
        #pragma unroll
        for (int i = 0; i < 8; i++) {
            float val = __half2float(xh[i]) * rcp[i]
                      + sgn * __half2float(rh[i]) * rsp[i];
            out8[i] = __float2half_rn(val);
        }
        *(uint4*)(kcat + (size_t)row * QK_D + NOPE_D + dr0) = *(uint4*)out8;
    } else {
        // trans_v tile: 32x32
        const int vb = bid - (NQN + NQR + NKN + NKR);
        const int tx = tid & 31;
        const int ty = tid >> 5;
        const int c0 = (vb % (512/32)) * 32;
        const int r0 = (vb / (512/32)) * 32;
        for (int i = ty; i < 32; i += 8)
            tile[i][tx] =
                __half2float(kvup[(size_t)(r0 + i) * N_KVUP + VOFF + c0 + tx]);
        __syncthreads();
        const int b = r0 >> 11;
        for (int i = ty; i < 32; i += 8)
            vt[(size_t)(b * 512 + c0 + i) * TT + (r0 & 2047) + tx] =
                __float2half_rn(tile[tx][i]);
    }
}

// ------------------------- fp16 tensor-core GEMM (mma.sync) -----------------
// R11 configuration (measured plateau): block 128x128, 8 warps of 64x32,
// 256 threads, 3-stage cp.async ring, 2 CTAs/SM, K-chunk = 32 halfs.
#define LDH 40                              // half pitch (80 B/row)
#define TSH (128*LDH)                       // halfs per operand per stage
#define GST3 3
#define GH_SMEM (GST3 * 2 * TSH * sizeof(__half))   // 61440 B

__global__ __launch_bounds__(256, 2) void gemm_f16(
    const __half* __restrict__ A, int lda,
    const __half* __restrict__ Bt,
    void* __restrict__ Cp, int N, int K, int c_half)
{
    extern __shared__ __half smh[];

    const int tid  = threadIdx.x;
    const int lane = tid & 31;
    const int wid  = tid >> 5;
    const int bx = blockIdx.x, by = blockIdx.y;

    const int m0 = (wid & 1) * 64;
    const int n0 = (wid >> 1) * 32;

    const int rselA = ((lane >> 3) & 1) * 8 + (lane & 7);
    const int cselA = (lane >> 4) * 8;              // halfs
    const int rselB = ((lane >> 4) & 1) * 8 + (lane & 7);
    const int cselB = ((lane >> 3) & 1) * 8;        // halfs

    const int l_row = tid >> 1;
    const int l_col = (tid & 1) * 16;               // halfs (32 B)

    const __half* Agb = A  + (size_t)(by * 128 + l_row) * lda + l_col;
    const __half* Bgb = Bt + (size_t)(bx * 128 + l_row) * K   + l_col;

    float acc[4][4][4];
    #pragma unroll
    for (int i = 0; i < 4; i++)
        #pragma unroll
        for (int j = 0; j < 4; j++)
            #pragma unroll
            for (int r = 0; r < 4; r++) acc[i][j][r] = 0.f;

    const int nch = K >> 5;

    // prologue: stages 0,1
    #pragma unroll
    for (int p = 0; p < 2; p++) {
        __half* Asb = smh + p * 2 * TSH + l_row * LDH + l_col;
        __half* Bsb = Asb + TSH;
        const __half* Ag = Agb + p * 32;
        const __half* Bg = Bgb + p * 32;
        #pragma unroll
        for (int i = 0; i < 2; i++) cp_async16(Asb + i*8, Ag + i*8);
        #pragma unroll
        for (int i = 0; i < 2; i++) cp_async16(Bsb + i*8, Bg + i*8);
        cp_commit();
    }

    int s = 0, s2 = 2;
    for (int ch = 0; ch < nch; ch++) {
        cp_wait<1>();
        __syncthreads();

        if (ch + 2 < nch) {
            const int k0 = (ch + 2) << 5;
            __half* Asb = smh + s2 * 2 * TSH + l_row * LDH + l_col;
            __half* Bsb = Asb + TSH;
            const __half* Ag = Agb + k0;
            const __half* Bg = Bgb + k0;
            #pragma unroll
            for (int i = 0; i < 2; i++) cp_async16(Asb + i*8, Ag + i*8);
            #pragma unroll
            for (int i = 0; i < 2; i++) cp_async16(Bsb + i*8, Bg + i*8);
        }
        cp_commit();

        const __half* Asb = smh + s * 2 * TSH;
        const __half* Bsb = Asb + TSH;

        #pragma unroll
        for (int kk = 0; kk < 2; kk++) {
            uint32_t af[4][4], bf[4][2];
            #pragma unroll
            for (int mi = 0; mi < 4; mi++) {
                LDMX4(af[mi][0], af[mi][1], af[mi][2], af[mi][3],
                      s2u(Asb + (m0 + mi*16 + rselA) * LDH + kk*16 + cselA));
            }
            #pragma unroll
            for (int nip = 0; nip < 2; nip++) {
                LDMX4(bf[2*nip][0], bf[2*nip][1], bf[2*nip+1][0], bf[2*nip+1][1],
                      s2u(Bsb + (n0 + nip*16 + rselB) * LDH + kk*16 + cselB));
            }
            #pragma unroll
            for (int mi = 0; mi < 4; mi++)
                #pragma unroll
                for (int ni = 0; ni < 4; ni++)
                    MMA_F16(acc[mi][ni], af[mi], bf[ni]);
        }
        s  = (s  == GST3-1) ? 0 : s  + 1;
        s2 = (s2 == GST3-1) ? 0 : s2 + 1;
    }

    const int crow = by * 128 + m0 + (lane >> 2);
    const int ccol = bx * 128 + n0 + (lane & 3) * 2;
    if (c_half) {
        __half* C = (__half*)Cp;
        #pragma unroll
        for (int mi = 0; mi < 4; mi++) {
            #pragma unroll
            for (int ni = 0; ni < 4; ni++) {
                const int r = crow + mi * 16;
                const int c = ccol + ni * 8;
                *(__half2*)(C + (size_t)r * N + c) =
                    __floats2half2_rn(acc[mi][ni][0], acc[mi][ni][1]);
                *(__half2*)(C + (size_t)(r + 8) * N + c) =
                    __floats2half2_rn(acc[mi][ni][2], acc[mi][ni][3]);
            }
        }
    } else {
        float* C = (float*)Cp;
        #pragma unroll
        for (int mi = 0; mi < 4; mi++) {
            #pragma unroll
            for (int ni = 0; ni < 4; ni++) {
                const int r = crow + mi * 16;
                const int c = ccol + ni * 8;
                *(float2*)(C + (size_t)r * N + c) =
                    make_float2(acc[mi][ni][0], acc[mi][ni][1]);
                *(float2*)(C + (size_t)(r + 8) * N + c) =
                    make_float2(acc[mi][ni][2], acc[mi][ni][3]);
            }
        }
    }
}

// ------------------------- flash attention (fp16 mma, K-tile 64) ------------
// R11 configuration (measured best: 2 CTAs/SM). Single-buffered pipeline:
// K_{jt+1} issued during PV_jt, V_{jt+1} issued after end-of-iter barrier.
#define LQH 200
#define LKH 200
#define LVTH 72
#define LPH 72
#define QS_SZ (128*LQH)
#define KS_SZ (64*LKH)
#define VTS_SZ (128*LVTH)
#define PS_SZ (128*LPH)
#define ATTN_SMEM ((QS_SZ + KS_SZ + VTS_SZ + PS_SZ) * sizeof(__half))

__global__ __launch_bounds__(256) void flash_attn_mma(
    const __half* __restrict__ q, const __half* __restrict__ k,
    const __half* __restrict__ vt, __half* __restrict__ out)
{
    extern __shared__ __half sh[];
    __half* Qs  = sh;
    __half* Ks  = sh + QS_SZ;
    __half* Vts = Ks + KS_SZ;
    __half* Ps  = Vts + VTS_SZ;

    const int bid  = blockIdx.x;
    const int qi   = (TT/128 - 1) - (bid >> 5);   // big tiles scheduled first
    const int head = bid & 31;
    const int b = head / NH, h = head % NH;
    const int hkv = h / NREP;
    const int tid = threadIdx.x;
    const int lane = tid & 31, wid = tid >> 5;
    const int r = lane >> 2, t = lane & 3;
    const int qw = wid * 16;
    const int qrow0 = qi * 128;

    const int rselA = ((lane >> 3) & 1) * 8 + (lane & 7);
    const int cselA = (lane >> 4) * 8;
    const int rselB = ((lane >> 4) & 1) * 8 + (lane & 7);
    const int cselB = ((lane >> 3) & 1) * 8;

    const __half* qbase = q + ((size_t)head * TT + qrow0) * QK_D;
    const __half* kbase = k + ((size_t)(b * NKV + hkv) * TT) * QK_D;
    const __half* vtbase = vt + (size_t)(b * 512 + hkv * 128) * TT;

    // prefetch: Q (group), K0 (group), V0 (group). 16B = 8 halfs per cp.
    for (int i = tid; i < 128 * 24; i += 256) {
        int rr = i / 24, c8 = i % 24;
        cp_async16(Qs + rr * LQH + c8 * 8, qbase + (size_t)rr * QK_D + c8 * 8);
    }
    cp_commit();
    for (int i = tid; i < 64 * 24; i += 256) {
        int rr = i / 24, c8 = i % 24;
        cp_async16(Ks + rr * LKH + c8 * 8, kbase + (size_t)rr * QK_D + c8 * 8);
    }
    cp_commit();
    for (int i = tid; i < 128 * 8; i += 256) {
        int rr = i >> 3, c8 = i & 7;
        cp_async16(Vts + rr * LVTH + c8 * 8, vtbase + (size_t)rr * TT + c8 * 8);
    }
    cp_commit();

    float m0 = -1e30f, m1 = -1e30f, l0 = 0.f, l1 = 0.f;
    float oacc[16][4];
    #pragma unroll
    for (int j = 0; j < 16; j++)
        #pragma unroll
        for (int c = 0; c < 4; c++) oacc[j][c] = 0.f;

    const int niter = 2 * qi + 2;
    for (int jt = 0; jt < niter; jt++) {
        const int krow0 = jt * 64;

        cp_wait<1>();          // Q + K_jt complete (V_jt may be in flight)
        __syncthreads();

        // ---- S = Q @ K^T ----
        float sacc[8][4];
        #pragma unroll
        for (int j = 0; j < 8; j++)
            #pragma unroll
            for (int c = 0; c < 4; c++) sacc[j][c] = 0.f;

        #pragma unroll 2
        for (int kc = 0; kc < 12; kc++) {
            uint32_t a[4];
            LDMX4(a[0], a[1], a[2], a[3],
                  s2u(Qs + (qw + rselA) * LQH + kc*16 + cselA));
            #pragma unroll
            for (int jp = 0; jp < 4; jp++) {
                uint32_t b0[2], b1[2];
                LDMX4(b0[0], b0[1], b1[0], b1[1],
                      s2u(Ks + (jp*16 + rselB) * LKH + kc*16 + cselB));
                MMA_F16(sacc[2*jp],   a, b0);
                MMA_F16(sacc[2*jp+1], a, b1);
            }
        }

        // ---- mask + online softmax ----
        const int gr0 = qrow0 + qw + r;
        const bool need_mask = (jt >= 2 * qi);
        float mx0 = m0, mx1 = m1;
        #pragma unroll
        for (int j = 0; j < 8; j++) {
            if (need_mask) {
                int gc = krow0 + 8 * j + 2 * t;
                if (gc     > gr0)     sacc[j][0] = -1e30f;
                if (gc + 1 > gr0)     sacc[j][1] = -1e30f;
                if (gc     > gr0 + 8) sacc[j][2] = -1e30f;
                if (gc + 1 > gr0 + 8) sacc[j][3] = -1e30f;
            }
            mx0 = fmaxf(mx0, fmaxf(sacc[j][0], sacc[j][1]));
            mx1 = fmaxf(mx1, fmaxf(sacc[j][2], sacc[j][3]));
        }
        mx0 = fmaxf(mx0, __shfl_xor_sync(0xffffffffu, mx0, 1));
        mx0 = fmaxf(mx0, __shfl_xor_sync(0xffffffffu, mx0, 2));
        mx1 = fmaxf(mx1, __shfl_xor_sync(0xffffffffu, mx1, 1));
        mx1 = fmaxf(mx1, __shfl_xor_sync(0xffffffffu, mx1, 2));

        float alpha0 = __expf(m0 - mx0);
        float alpha1 = __expf(m1 - mx1);
        m0 = mx0; m1 = mx1;

        float ls0 = 0.f, ls1 = 0.f;
        __half2* pp = (__half2*)(Ps + (qw + r) * LPH);
        #pragma unroll
        for (int j = 0; j < 8; j++) {
            float p0 = __expf(sacc[j][0] - mx0);
            float p1 = __expf(sacc[j][1] - mx0);
            float p2 = __expf(sacc[j][2] - mx1);
            float p3 = __expf(sacc[j][3] - mx1);
            ls0 += p0 + p1; ls1 += p2 + p3;
            pp[4*j + t]                = __floats2half2_rn(p0, p1);
            pp[8*(LPH/2) + 4*j + t]    = __floats2half2_rn(p2, p3);
        }
        ls0 += __shfl_xor_sync(0xffffffffu, ls0, 1);
        ls0 += __shfl_xor_sync(0xffffffffu, ls0, 2);
        ls1 += __shfl_xor_sync(0xffffffffu, ls1, 1);
        ls1 += __shfl_xor_sync(0xffffffffu, ls1, 2);
        l0 = l0 * alpha0 + ls0;
        l1 = l1 * alpha1 + ls1;

        #pragma unroll
        for (int j = 0; j < 16; j++) {
            oacc[j][0] *= alpha0; oacc[j][1] *= alpha0;
            oacc[j][2] *= alpha1; oacc[j][3] *= alpha1;
        }

        cp_wait<0>();          // V_jt complete; all threads done reading Ks
        __syncthreads();

        // issue K_{jt+1} now — PV does not touch Ks
        if (jt + 1 < niter) {
            const int kn0 = (jt + 1) * 64;
            for (int i = tid; i < 64 * 24; i += 256) {
                int rr = i / 24, c8 = i % 24;
                cp_async16(Ks + rr * LKH + c8 * 8,
                           kbase + (size_t)(kn0 + rr) * QK_D + c8 * 8);
            }
            cp_commit();
        }

        // ---- O += P @ V ----
        #pragma unroll
        for (int kc = 0; kc < 4; kc++) {
            uint32_t a[4];
            LDMX4(a[0], a[1], a[2], a[3],
                  s2u(Ps + (qw + rselA) * LPH + kc*16 + cselA));
            #pragma unroll
            for (int jp = 0; jp < 8; jp++) {
                uint32_t b0[2], b1[2];
                LDMX4(b0[0], b0[1], b1[0], b1[1],
                      s2u(Vts + (jp*16 + rselB) * LVTH + kc*16 + cselB));
                MMA_F16(oacc[2*jp],   a, b0);
                MMA_F16(oacc[2*jp+1], a, b1);
            }
        }
        __syncthreads();       // all threads done reading Vts/Ps

        // issue V_{jt+1} — lands during S_{jt+1}
        if (jt + 1 < niter) {
            const int kn0 = (jt + 1) * 64;
            for (int i = tid; i < 128 * 8; i += 256) {
                int rr = i >> 3, c8 = i & 7;
                cp_async16(Vts + rr * LVTH + c8 * 8,
                           vtbase + (size_t)rr * TT + kn0 + c8 * 8);
            }
            cp_commit();
        }
    }

    const float inv0 = 1.0f / l0;
    const float inv1 = 1.0f / l1;
    const int gr0 = qrow0 + qw + r;
    __half* ob = out + ((size_t)b * TT + gr0) * (NH * V_D) + h * V_D;
    #pragma unroll
    for (int j = 0; j < 16; j++) {
        int c = 8 * j + 2 * t;
        *(__half2*)(ob + c) =
            __floats2half2_rn(oacc[j][0] * inv0, oacc[j][1] * inv0);
        *(__half2*)(ob + (size_t)8 * (NH * V_D) + c) =
            __floats2half2_rn(oacc[j][2] * inv1, oacc[j][3] * inv1);
    }
}

// ------------------------- launch -------------------------------------------
extern "C" void kernel_launch(void* const* d_in, const int* in_sizes, int n_in,
                              void* d_out, int out_size)
{
    const float* x         = (const float*)d_in[0];
    const float* W_kv_down = (const float*)d_in[1];
    const float* W_k_nope  = (const float*)d_in[2];
    const float* W_k_rope  = (const float*)d_in[3];
    const float* W_v       = (const float*)d_in[4];
    const float* W_q_down  = (const float*)d_in[5];
    const float* W_q_nope  = (const float*)d_in[6];
    const float* W_q_rope  = (const float*)d_in[7];
    const float* W_o       = (const float*)d_in[8];
    float* out = (float*)d_out;

    __half *w_down, *w_kv, *w_q, *w_o, *x_r, *cdown, *kvup, *qup;
    __half *qcat, *kcat, *vt, *attn;
    float *rc, *rs;
    cudaGetSymbolAddress((void**)&w_down, g_w_down);
    cudaGetSymbolAddress((void**)&w_kv,   g_w_kv);
    cudaGetSymbolAddress((void**)&w_q,    g_w_q);
    cudaGetSymbolAddress((void**)&w_o,    g_w_o);
    cudaGetSymbolAddress((void**)&x_r,    g_x_r);
    cudaGetSymbolAddress((void**)&cdown,  g_cdown);
    cudaGetSymbolAddress((void**)&kvup,   g_kvup);
    cudaGetSymbolAddress((void**)&qup,    g_qup);
    cudaGetSymbolAddress((void**)&qcat,   g_qcat);
    cudaGetSymbolAddress((void**)&kcat,   g_kcat);
    cudaGetSymbolAddress((void**)&vt,     g_vt);
    cudaGetSymbolAddress((void**)&attn,   g_attn);
    cudaGetSymbolAddress((void**)&rc,     g_ropec);
    cudaGetSymbolAddress((void**)&rs,     g_ropes);

    cudaFuncSetAttribute(gemm_f16, cudaFuncAttributeMaxDynamicSharedMemorySize,
                         (int)GH_SMEM);
    cudaFuncSetAttribute(flash_attn_mma, cudaFuncAttributeMaxDynamicSharedMemorySize,
                         (int)ATTN_SMEM);

    // ---- merged weight transpose+convert (single launch) ----
    {
        TJobs jobs;
        const float* srcs[8] = {W_kv_down, W_q_down, W_k_nope, W_k_rope,
                                W_v, W_q_nope, W_q_rope, W_o};
        __half* dsts[8] = {w_down, w_down, w_kv, w_kv, w_kv, w_q, w_q, w_o};
        int Rs[8]    = {DIM, DIM, KV_RANK, KV_RANK, KV_RANK, Q_RANK, Q_RANK, NH*V_D};
        int Cs[8]    = {KV_RANK, Q_RANK, NKV*NOPE_D, NKV*ROPE_D, NKV*V_D,
                        NH*NOPE_D, NH*ROPE_D, DIM};
        int noffs[8] = {0, KV_RANK, 0, NKV*NOPE_D, VOFF, 0, NH*NOPE_D, 0};
        int cum = 0;
        for (int k = 0; k < 8; k++) {
            jobs.src[k] = srcs[k]; jobs.dst[k] = dsts[k];
            jobs.R[k] = Rs[k]; jobs.C[k] = Cs[k]; jobs.noff[k] = noffs[k];
            jobs.start[k] = cum;
            cum += (Rs[k] / 32) * (Cs[k] / 32);
        }
        jobs.njobs = 8;
        trans_half_multi<<<cum, dim3(32, 8)>>>(jobs);
    }
    copy_half4<<<592, 256>>>((__half2*)x_r, (const float4*)x, MROWS * DIM / 4);
    rope_table<<<(TT * ROPE_D + 255) / 256, 256>>>(rc, rs);

    // ---- fused down projection: [kv_c | q_c] ----
    gemm_f16<<<dim3(N_DOWN/128, MROWS/128), 256, GH_SMEM>>>(
        x_r, DIM, w_down, cdown, N_DOWN, DIM, 1);

    // ---- fused up projections ----
    gemm_f16<<<dim3(N_KVUP/128, MROWS/128), 256, GH_SMEM>>>(
        cdown, N_DOWN, w_kv, kvup, N_KVUP, KV_RANK, 1);
    gemm_f16<<<dim3(N_QUP/128, MROWS/128), 256, GH_SMEM>>>(
        cdown + KV_RANK, N_DOWN, w_q, qup, N_QUP, Q_RANK, 1);

    // ---- fused RoPE assembly + V transpose (single launch, vectorized) ----
    assemble_all<<<NQN + NQR + NKN + NKR + NTV, 256>>>(
        qup, kvup, rc, rs, qcat, kcat, vt);

    // ---- attention (1D grid, largest tiles first) ----
    flash_attn_mma<<<(TT/128) * BB * NH, 256, ATTN_SMEM>>>(qcat, kcat, vt, attn);

    // ---- output projection (float out) ----
    gemm_f16<<<dim3(DIM/128, MROWS/128), 256, GH_SMEM>>>(
        attn, NH*V_D, w_o, out, DIM, NH*V_D, 0);
}

// round 16
// speedup vs baseline: 1.1090x; 1.0465x over previous
#include <cuda_runtime.h>
#include <cuda_fp16.h>
#include <math.h>
#include <stdint.h>

// Problem constants
#define BB 2
#define TT 2048
#define DIM 2048
#define NH 16
#define NKV 4
#define NREP 4
#define ROPE_D 64
#define NOPE_D 128
#define V_D 128
#define QK_D 192
#define KV_RANK 512
#define Q_RANK 1536
#define MROWS (BB*TT)   // 4096

// fused widths
#define N_DOWN 2048            // [kv_c(512) | q_c(1536)]
#define N_KVUP 1280            // [k_nope(512) | k_rope(256) | v(512)]
#define N_QUP  3072            // [q_nope(2048) | q_rope(1024)]
#define VOFF   (NKV*NOPE_D + NKV*ROPE_D)   // 768

// ------------------------- scratch (static device memory) -------------------
__device__ __half g_w_down[N_DOWN * DIM];       // transposed [N][K], fp16
__device__ __half g_w_kv  [N_KVUP * KV_RANK];
__device__ __half g_w_q   [N_QUP * Q_RANK];
__device__ __half g_w_o   [DIM * (NH*V_D)];
__device__ __half g_x_r   [MROWS * DIM];
__device__ __half g_cdown [MROWS * N_DOWN];
__device__ __half g_kvup  [MROWS * N_KVUP];
__device__ __half g_qup   [MROWS * N_QUP];
__device__ __half g_qcat  [BB*NH  * TT * QK_D];
__device__ __half g_kcat  [BB*NKV * TT * QK_D];
__device__ __half g_vt    [BB*NKV * V_D * TT];
__device__ __half g_attn  [MROWS * (NH*V_D)];
__device__ float  g_ropec [TT * ROPE_D];
__device__ float  g_ropes [TT * ROPE_D];

// ------------------------- common PTX helpers -------------------------------
__device__ __forceinline__ uint32_t s2u(const void* p) {
    return (uint32_t)__cvta_generic_to_shared(p);
}
__device__ __forceinline__ void cp_async16(void* smem, const void* gmem) {
    asm volatile("cp.async.cg.shared.global [%0], [%1], 16;\n"
                 :: "r"(s2u(smem)), "l"(gmem));
}
__device__ __forceinline__ void cp_commit() {
    asm volatile("cp.async.commit_group;\n" ::: "memory");
}
template<int N>
__device__ __forceinline__ void cp_wait() {
    asm volatile("cp.async.wait_group %0;\n" :: "n"(N) : "memory");
}

#define LDMX4(r0, r1, r2, r3, addr) \
    asm volatile("ldmatrix.sync.aligned.m8n8.x4.shared.b16 {%0,%1,%2,%3}, [%4];" \
                 : "=r"(r0), "=r"(r1), "=r"(r2), "=r"(r3) : "r"(addr))

#define MMA_F16(c, a, b) \
    asm volatile("mma.sync.aligned.m16n8k16.row.col.f32.f16.f16.f32 " \
                 "{%0,%1,%2,%3},{%4,%5,%6,%7},{%8,%9},{%0,%1,%2,%3};" \
                 : "+f"((c)[0]), "+f"((c)[1]), "+f"((c)[2]), "+f"((c)[3]) \
                 : "r"((a)[0]), "r"((a)[1]), "r"((a)[2]), "r"((a)[3]), \
                   "r"((b)[0]), "r"((b)[1]))

// ------------------------- prep kernels --------------------------------------
// fused: rope table (first TBL_B blocks) + x float->half copy
#define TBL_B ((TT*ROPE_D + 255) / 256)        // 512
__global__ void prep_misc(float* __restrict__ rc, float* __restrict__ rs,
                          __half2* __restrict__ xdst, const float4* __restrict__ xsrc,
                          int total4)
{
    const int bid = blockIdx.x;
    if (bid < TBL_B) {
        int idx = bid * 256 + threadIdx.x;
        int t = idx >> 6, dr = idx & 63;
        int j = dr & 31;
        float theta = exp2f(-0.4152410118609203f * (float)j);  // 10000^(-j/32)
        float ang = (float)t * theta;
        rc[idx] = cosf(ang);
        rs[idx] = sinf(ang);
    } else {
        for (int i = (bid - TBL_B) * 256 + threadIdx.x; i < total4;
             i += (gridDim.x - TBL_B) * 256) {
            float4 v = xsrc[i];
            xdst[2*i]   = __floats2half2_rn(v.x, v.y);
            xdst[2*i+1] = __floats2half2_rn(v.z, v.w);
        }
    }
}

// merged transpose+convert: 8 jobs in one launch
struct TJobs {
    const float* src[8];
    __half* dst[8];
    int R[8], C[8], noff[8], start[8];
    int njobs;
};

__global__ void trans_half_multi(TJobs jobs)
{
    __shared__ float tile[32][33];
    const int bid = blockIdx.x;
    int jj = 0;
    #pragma unroll
    for (int k = 1; k < 8; k++)
        if (k < jobs.njobs && bid >= jobs.start[k]) jj = k;
    const int local = bid - jobs.start[jj];
    const int C = jobs.C[jj], R = jobs.R[jj], noff = jobs.noff[jj];
    const int tx = C >> 5;
    const int c0 = (local % tx) * 32;
    const int r0 = (local / tx) * 32;
    const float* src = jobs.src[jj];
    __half* dst = jobs.dst[jj];

    for (int i = threadIdx.y; i < 32; i += 8)
        tile[i][threadIdx.x] = src[(size_t)(r0 + i) * C + c0 + threadIdx.x];
    __syncthreads();
    for (int i = threadIdx.y; i < 32; i += 8)
        dst[(size_t)(noff + c0 + i) * R + r0 + threadIdx.x] =
            __float2half_rn(tile[threadIdx.x][i]);
}

// ---- fused assembly (vectorized, div/mod-free) ------------------------------
#define NQN (BB*NH*TT*16/256)    // 4096
#define NQR (BB*NH*TT*8/256)     // 2048
#define NKN (BB*NKV*TT*16/256)   // 1024
#define NKR (BB*NKV*TT*8/256)    // 512
#define NTV ((512/32) * (MROWS/32))   // 2048

__global__ void assemble_all(const __half* __restrict__ qup,
                             const __half* __restrict__ kvup,
                             const float* __restrict__ rc,
                             const float* __restrict__ rs,
                             __half* __restrict__ qcat,
                             __half* __restrict__ kcat,
                             __half* __restrict__ vt)
{
    __shared__ float tile[32][33];
    const int bid = blockIdx.x;
    const int tid = threadIdx.x;
    const float scale = rsqrtf((float)QK_D);

    if (bid < NQN) {
        int gid = bid * 256 + tid;
        int row = gid >> 4, seg = gid & 15;
        int h = (row >> 11) & 15, t = row & 2047, b = row >> 15;
        uint4 v = *(const uint4*)(qup + (size_t)(b * TT + t) * N_QUP
                                  + h * NOPE_D + seg * 8);
        __half2* hv = (__half2*)&v;
        #pragma unroll
        for (int i = 0; i < 4; i++) {
            float2 f = __half22float2(hv[i]);
            hv[i] = __floats2half2_rn(f.x * scale, f.y * scale);
        }
        *(uint4*)(qcat + (size_t)row * QK_D + seg * 8) = v;
    } else if (bid < NQN + NQR) {
        int gid = (bid - NQN) * 256 + tid;
        int row = gid >> 3, part = gid & 7;
        int h = (row >> 11) & 15, t = row & 2047, b = row >> 15;
        int dr0 = part * 8;
        const __half* base = qup + (size_t)(b * TT + t) * N_QUP
                             + NH * NOPE_D + h * ROPE_D;
        uint4 xv = *(const uint4*)(base + dr0);
        uint4 rv = *(const uint4*)(base + ((part < 4) ? dr0 + 32 : dr0 - 32));
        const float sgn = (part < 4) ? -1.f : 1.f;
        const float* rcp = rc + t * ROPE_D + dr0;
        const float* rsp = rs + t * ROPE_D + dr0;
        const __half* xh = (const __half*)&xv;
        const __half* rh = (const __half*)&rv;
        __half out8[8];
        #pragma unroll
        for (int i = 0; i < 8; i++) {
            float val = __half2float(xh[i]) * rcp[i]
                      + sgn * __half2float(rh[i]) * rsp[i];
            out8[i] = __float2half_rn(val * scale);
        }
        *(uint4*)(qcat + (size_t)row * QK_D + NOPE_D + dr0) = *(uint4*)out8;
    } else if (bid < NQN + NQR + NKN) {
        int gid = (bid - NQN - NQR) * 256 + tid;
        int row = gid >> 4, seg = gid & 15;
        int h = (row >> 11) & 3, t = row & 2047, b = row >> 13;
        uint4 v = *(const uint4*)(kvup + (size_t)(b * TT + t) * N_KVUP
                                  + h * NOPE_D + seg * 8);
        *(uint4*)(kcat + (size_t)row * QK_D + seg * 8) = v;
    } else if (bid < NQN + NQR + NKN + NKR) {
        int gid = (bid - NQN - NQR - NKN) * 256 + tid;
        int row = gid >> 3, part = gid & 7;
        int h = (row >> 11) & 3, t = row & 2047, b = row >> 13;
        int dr0 = part * 8;
        const __half* base = kvup + (size_t)(b * TT + t) * N_KVUP
                             + NKV * NOPE_D + h * ROPE_D;
        uint4 xv = *(const uint4*)(base + dr0);
        uint4 rv = *(const uint4*)(base + ((part < 4) ? dr0 + 32 : dr0 - 32));
        const float sgn = (part < 4) ? -1.f : 1.f;
        const float* rcp = rc + t * ROPE_D + dr0;
        const float* rsp = rs + t * ROPE_D + dr0;
        const __half* xh = (const __half*)&xv;
        const __half* rh = (const __half*)&rv;
        __half out8[8];
        #pragma unroll
        for (int i = 0; i < 8; i++) {
            float val = __half2float(xh[i]) * rcp[i]
                      + sgn * __half2float(rh[i]) * rsp[i];
            out8[i] = __float2half_rn(val);
        }
        *(uint4*)(kcat + (size_t)row * QK_D + NOPE_D + dr0) = *(uint4*)out8;
    } else {
        const int vb = bid - (NQN + NQR + NKN + NKR);
        const int tx = tid & 31;
        const int ty = tid >> 5;
        const int c0 = (vb % (512/32)) * 32;
        const int r0 = (vb / (512/32)) * 32;
        for (int i = ty; i < 32; i += 8)
            tile[i][tx] =
                __half2float(kvup[(size_t)(r0 + i) * N_KVUP + VOFF + c0 + tx]);
        __syncthreads();
        const int b = r0 >> 11;
        for (int i = ty; i < 32; i += 8)
            vt[(size_t)(b * 512 + c0 + i) * TT + (r0 & 2047) + tx] =
                __float2half_rn(tile[tx][i]);
    }
}

// ------------------------- fp16 tensor-core GEMM (mma.sync) -----------------
// R11/R15 plateau config: block 128x128, 8 warps of 64x32, 256 threads,
// 3-stage cp.async ring, 2 CTAs/SM, K-chunk = 32 halfs.
#define LDH 40                              // half pitch (80 B/row)
#define TSH (128*LDH)                       // halfs per operand per stage
#define GST3 3
#define GH_SMEM (GST3 * 2 * TSH * sizeof(__half))   // 61440 B

// GEMM body shared by both entry points. 1-D tile index.
__device__ __forceinline__ void gemm_body(
    const __half* __restrict__ A, int lda,
    const __half* __restrict__ Bt,
    void* __restrict__ Cp, int N, int K, int c_half,
    int tile, __half* smh)
{
    const int tid  = threadIdx.x;
    const int lane = tid & 31;
    const int wid  = tid >> 5;
    const int nbx = N >> 7;
    const int bx = tile % nbx, by = tile / nbx;

    const int m0 = (wid & 1) * 64;
    const int n0 = (wid >> 1) * 32;

    const int rselA = ((lane >> 3) & 1) * 8 + (lane & 7);
    const int cselA = (lane >> 4) * 8;
    const int rselB = ((lane >> 4) & 1) * 8 + (lane & 7);
    const int cselB = ((lane >> 3) & 1) * 8;

    const int l_row = tid >> 1;
    const int l_col = (tid & 1) * 16;

    const __half* Agb = A  + (size_t)(by * 128 + l_row) * lda + l_col;
    const __half* Bgb = Bt + (size_t)(bx * 128 + l_row) * K   + l_col;

    float acc[4][4][4];
    #pragma unroll
    for (int i = 0; i < 4; i++)
        #pragma unroll
        for (int j = 0; j < 4; j++)
            #pragma unroll
            for (int r = 0; r < 4; r++) acc[i][j][r] = 0.f;

    const int nch = K >> 5;

    #pragma unroll
    for (int p = 0; p < 2; p++) {
        __half* Asb = smh + p * 2 * TSH + l_row * LDH + l_col;
        __half* Bsb = Asb + TSH;
        const __half* Ag = Agb + p * 32;
        const __half* Bg = Bgb + p * 32;
        #pragma unroll
        for (int i = 0; i < 2; i++) cp_async16(Asb + i*8, Ag + i*8);
        #pragma unroll
        for (int i = 0; i < 2; i++) cp_async16(Bsb + i*8, Bg + i*8);
        cp_commit();
    }

    int s = 0, s2 = 2;
    for (int ch = 0; ch < nch; ch++) {
        cp_wait<1>();
        __syncthreads();

        if (ch + 2 < nch) {
            const int k0 = (ch + 2) << 5;
            __half* Asb = smh + s2 * 2 * TSH + l_row * LDH + l_col;
            __half* Bsb = Asb + TSH;
            const __half* Ag = Agb + k0;
            const __half* Bg = Bgb + k0;
            #pragma unroll
            for (int i = 0; i < 2; i++) cp_async16(Asb + i*8, Ag + i*8);
            #pragma unroll
            for (int i = 0; i < 2; i++) cp_async16(Bsb + i*8, Bg + i*8);
        }
        cp_commit();

        const __half* Asb = smh + s * 2 * TSH;
        const __half* Bsb = Asb + TSH;

        #pragma unroll
        for (int kk = 0; kk < 2; kk++) {
            uint32_t af[4][4], bf[4][2];
            #pragma unroll
            for (int mi = 0; mi < 4; mi++) {
                LDMX4(af[mi][0], af[mi][1], af[mi][2], af[mi][3],
                      s2u(Asb + (m0 + mi*16 + rselA) * LDH + kk*16 + cselA));
            }
            #pragma unroll
            for (int nip = 0; nip < 2; nip++) {
                LDMX4(bf[2*nip][0], bf[2*nip][1], bf[2*nip+1][0], bf[2*nip+1][1],
                      s2u(Bsb + (n0 + nip*16 + rselB) * LDH + kk*16 + cselB));
            }
            #pragma unroll
            for (int mi = 0; mi < 4; mi++)
                #pragma unroll
                for (int ni = 0; ni < 4; ni++)
                    MMA_F16(acc[mi][ni], af[mi], bf[ni]);
        }
        s  = (s  == GST3-1) ? 0 : s  + 1;
        s2 = (s2 == GST3-1) ? 0 : s2 + 1;
    }

    const int crow = by * 128 + m0 + (lane >> 2);
    const int ccol = bx * 128 + n0 + (lane & 3) * 2;
    if (c_half) {
        __half* C = (__half*)Cp;
        #pragma unroll
        for (int mi = 0; mi < 4; mi++) {
            #pragma unroll
            for (int ni = 0; ni < 4; ni++) {
                const int r = crow + mi * 16;
                const int c = ccol + ni * 8;
                *(__half2*)(C + (size_t)r * N + c) =
                    __floats2half2_rn(acc[mi][ni][0], acc[mi][ni][1]);
                *(__half2*)(C + (size_t)(r + 8) * N + c) =
                    __floats2half2_rn(acc[mi][ni][2], acc[mi][ni][3]);
            }
        }
    } else {
        float* C = (float*)Cp;
        #pragma unroll
        for (int mi = 0; mi < 4; mi++) {
            #pragma unroll
            for (int ni = 0; ni < 4; ni++) {
                const int r = crow + mi * 16;
                const int c = ccol + ni * 8;
                *(float2*)(C + (size_t)r * N + c) =
                    make_float2(acc[mi][ni][0], acc[mi][ni][1]);
                *(float2*)(C + (size_t)(r + 8) * N + c) =
                    make_float2(acc[mi][ni][2], acc[mi][ni][3]);
            }
        }
    }
}

__global__ __launch_bounds__(256, 2) void gemm_f16(
    const __half* __restrict__ A, int lda,
    const __half* __restrict__ Bt,
    void* __restrict__ Cp, int N, int K, int c_half)
{
    extern __shared__ __half smh[];
    gemm_body(A, lda, Bt, Cp, N, K, c_half, blockIdx.x, smh);
}

// fused up-projections: q-up tiles first (long K), then kv-up tiles (short K)
#define QUP_TILES ((MROWS/128) * (N_QUP/128))    // 768
#define KVUP_TILES ((MROWS/128) * (N_KVUP/128))  // 320

__global__ __launch_bounds__(256, 2) void gemm_up_fused(
    const __half* __restrict__ cdown,
    const __half* __restrict__ w_q,
    const __half* __restrict__ w_kv,
    __half* __restrict__ qup,
    __half* __restrict__ kvup)
{
    extern __shared__ __half smh[];
    const int bid = blockIdx.x;
    if (bid < QUP_TILES) {
        gemm_body(cdown + KV_RANK, N_DOWN, w_q, qup, N_QUP, Q_RANK, 1, bid, smh);
    } else {
        gemm_body(cdown, N_DOWN, w_kv, kvup, N_KVUP, KV_RANK, 1,
                  bid - QUP_TILES, smh);
    }
}

// ------------------------- flash attention (fp16 mma, K-tile 64) ------------
#define LQH 200
#define LKH 200
#define LVTH 72
#define LPH 72
#define QS_SZ (128*LQH)
#define KS_SZ (64*LKH)
#define VTS_SZ (128*LVTH)
#define PS_SZ (128*LPH)
#define ATTN_SMEM ((QS_SZ + KS_SZ + VTS_SZ + PS_SZ) * sizeof(__half))

__global__ __launch_bounds__(256) void flash_attn_mma(
    const __half* __restrict__ q, const __half* __restrict__ k,
    const __half* __restrict__ vt, __half* __restrict__ out)
{
    extern __shared__ __half sh[];
    __half* Qs  = sh;
    __half* Ks  = sh + QS_SZ;
    __half* Vts = Ks + KS_SZ;
    __half* Ps  = Vts + VTS_SZ;

    const int bid  = blockIdx.x;
    const int qi   = (TT/128 - 1) - (bid >> 5);
    const int head = bid & 31;
    const int b = head / NH, h = head % NH;
    const int hkv = h / NREP;
    const int tid = threadIdx.x;
    const int lane = tid & 31, wid = tid >> 5;
    const int r = lane >> 2, t = lane & 3;
    const int qw = wid * 16;
    const int qrow0 = qi * 128;

    const int rselA = ((lane >> 3) & 1) * 8 + (lane & 7);
    const int cselA = (lane >> 4) * 8;
    const int rselB = ((lane >> 4) & 1) * 8 + (lane & 7);
    const int cselB = ((lane >> 3) & 1) * 8;

    const __half* qbase = q + ((size_t)head * TT + qrow0) * QK_D;
    const __half* kbase = k + ((size_t)(b * NKV + hkv) * TT) * QK_D;
    const __half* vtbase = vt + (size_t)(b * 512 + hkv * 128) * TT;

    for (int i = tid; i < 128 * 24; i += 256) {
        int rr = i / 24, c8 = i % 24;
        cp_async16(Qs + rr * LQH + c8 * 8, qbase + (size_t)rr * QK_D + c8 * 8);
    }
    cp_commit();
    for (int i = tid; i < 64 * 24; i += 256) {
        int rr = i / 24, c8 = i % 24;
        cp_async16(Ks + rr * LKH + c8 * 8, kbase + (size_t)rr * QK_D + c8 * 8);
    }
    cp_commit();
    for (int i = tid; i < 128 * 8; i += 256) {
        int rr = i >> 3, c8 = i & 7;
        cp_async16(Vts + rr * LVTH + c8 * 8, vtbase + (size_t)rr * TT + c8 * 8);
    }
    cp_commit();

    float m0 = -1e30f, m1 = -1e30f, l0 = 0.f, l1 = 0.f;
    float oacc[16][4];
    #pragma unroll
    for (int j = 0; j < 16; j++)
        #pragma unroll
        for (int c = 0; c < 4; c++) oacc[j][c] = 0.f;

    const int niter = 2 * qi + 2;
    for (int jt = 0; jt < niter; jt++) {
        const int krow0 = jt * 64;

        cp_wait<1>();
        __syncthreads();

        float sacc[8][4];
        #pragma unroll
        for (int j = 0; j < 8; j++)
            #pragma unroll
            for (int c = 0; c < 4; c++) sacc[j][c] = 0.f;

        #pragma unroll 2
        for (int kc = 0; kc < 12; kc++) {
            uint32_t a[4];
            LDMX4(a[0], a[1], a[2], a[3],
                  s2u(Qs + (qw + rselA) * LQH + kc*16 + cselA));
            #pragma unroll
            for (int jp = 0; jp < 4; jp++) {
                uint32_t b0[2], b1[2];
                LDMX4(b0[0], b0[1], b1[0], b1[1],
                      s2u(Ks + (jp*16 + rselB) * LKH + kc*16 + cselB));
                MMA_F16(sacc[2*jp],   a, b0);
                MMA_F16(sacc[2*jp+1], a, b1);
            }
        }

        const int gr0 = qrow0 + qw + r;
        const bool need_mask = (jt >= 2 * qi);
        float mx0 = m0, mx1 = m1;
        #pragma unroll
        for (int j = 0; j < 8; j++) {
            if (need_mask) {
                int gc = krow0 + 8 * j + 2 * t;
                if (gc     > gr0)     sacc[j][0] = -1e30f;
                if (gc + 1 > gr0)     sacc[j][1] = -1e30f;
                if (gc     > gr0 + 8) sacc[j][2] = -1e30f;
                if (gc + 1 > gr0 + 8) sacc[j][3] = -1e30f;
            }
            mx0 = fmaxf(mx0, fmaxf(sacc[j][0], sacc[j][1]));
            mx1 = fmaxf(mx1, fmaxf(sacc[j][2], sacc[j][3]));
        }
        mx0 = fmaxf(mx0, __shfl_xor_sync(0xffffffffu, mx0, 1));
        mx0 = fmaxf(mx0, __shfl_xor_sync(0xffffffffu, mx0, 2));
        mx1 = fmaxf(mx1, __shfl_xor_sync(0xffffffffu, mx1, 1));
        mx1 = fmaxf(mx1, __shfl_xor_sync(0xffffffffu, mx1, 2));

        float alpha0 = __expf(m0 - mx0);
        float alpha1 = __expf(m1 - mx1);
        m0 = mx0; m1 = mx1;

        float ls0 = 0.f, ls1 = 0.f;
        __half2* pp = (__half2*)(Ps + (qw + r) * LPH);
        #pragma unroll
        for (int j = 0; j < 8; j++) {
            float p0 = __expf(sacc[j][0] - mx0);
            float p1 = __expf(sacc[j][1] - mx0);
            float p2 = __expf(sacc[j][2] - mx1);
            float p3 = __expf(sacc[j][3] - mx1);
            ls0 += p0 + p1; ls1 += p2 + p3;
            pp[4*j + t]                = __floats2half2_rn(p0, p1);
            pp[8*(LPH/2) + 4*j + t]    = __floats2half2_rn(p2, p3);
        }
        ls0 += __shfl_xor_sync(0xffffffffu, ls0, 1);
        ls0 += __shfl_xor_sync(0xffffffffu, ls0, 2);
        ls1 += __shfl_xor_sync(0xffffffffu, ls1, 1);
        ls1 += __shfl_xor_sync(0xffffffffu, ls1, 2);
        l0 = l0 * alpha0 + ls0;
        l1 = l1 * alpha1 + ls1;

        #pragma unroll
        for (int j = 0; j < 16; j++) {
            oacc[j][0] *= alpha0; oacc[j][1] *= alpha0;
            oacc[j][2] *= alpha1; oacc[j][3] *= alpha1;
        }

        cp_wait<0>();
        __syncthreads();

        if (jt + 1 < niter) {
            const int kn0 = (jt + 1) * 64;
            for (int i = tid; i < 64 * 24; i += 256) {
                int rr = i / 24, c8 = i % 24;
                cp_async16(Ks + rr * LKH + c8 * 8,
                           kbase + (size_t)(kn0 + rr) * QK_D + c8 * 8);
            }
            cp_commit();
        }

        #pragma unroll
        for (int kc = 0; kc < 4; kc++) {
            uint32_t a[4];
            LDMX4(a[0], a[1], a[2], a[3],
                  s2u(Ps + (qw + rselA) * LPH + kc*16 + cselA));
            #pragma unroll
            for (int jp = 0; jp < 8; jp++) {
                uint32_t b0[2], b1[2];
                LDMX4(b0[0], b0[1], b1[0], b1[1],
                      s2u(Vts + (jp*16 + rselB) * LVTH + kc*16 + cselB));
                MMA_F16(oacc[2*jp],   a, b0);
                MMA_F16(oacc[2*jp+1], a, b1);
            }
        }
        __syncthreads();

        if (jt + 1 < niter) {
            const int kn0 = (jt + 1) * 64;
            for (int i = tid; i < 128 * 8; i += 256) {
                int rr = i >> 3, c8 = i & 7;
                cp_async16(Vts + rr * LVTH + c8 * 8,
                           vtbase + (size_t)rr * TT + kn0 + c8 * 8);
            }
            cp_commit();
        }
    }

    const float inv0 = 1.0f / l0;
    const float inv1 = 1.0f / l1;
    const int gr0 = qrow0 + qw + r;
    __half* ob = out + ((size_t)b * TT + gr0) * (NH * V_D) + h * V_D;
    #pragma unroll
    for (int j = 0; j < 16; j++) {
        int c = 8 * j + 2 * t;
        *(__half2*)(ob + c) =
            __floats2half2_rn(oacc[j][0] * inv0, oacc[j][1] * inv0);
        *(__half2*)(ob + (size_t)8 * (NH * V_D) + c) =
            __floats2half2_rn(oacc[j][2] * inv1, oacc[j][3] * inv1);
    }
}

// ------------------------- launch -------------------------------------------
extern "C" void kernel_launch(void* const* d_in, const int* in_sizes, int n_in,
                              void* d_out, int out_size)
{
    const float* x         = (const float*)d_in[0];
    const float* W_kv_down = (const float*)d_in[1];
    const float* W_k_nope  = (const float*)d_in[2];
    const float* W_k_rope  = (const float*)d_in[3];
    const float* W_v       = (const float*)d_in[4];
    const float* W_q_down  = (const float*)d_in[5];
    const float* W_q_nope  = (const float*)d_in[6];
    const float* W_q_rope  = (const float*)d_in[7];
    const float* W_o       = (const float*)d_in[8];
    float* out = (float*)d_out;

    __half *w_down, *w_kv, *w_q, *w_o, *x_r, *cdown, *kvup, *qup;
    __half *qcat, *kcat, *vt, *attn;
    float *rc, *rs;
    cudaGetSymbolAddress((void**)&w_down, g_w_down);
    cudaGetSymbolAddress((void**)&w_kv,   g_w_kv);
    cudaGetSymbolAddress((void**)&w_q,    g_w_q);
    cudaGetSymbolAddress((void**)&w_o,    g_w_o);
    cudaGetSymbolAddress((void**)&x_r,    g_x_r);
    cudaGetSymbolAddress((void**)&cdown,  g_cdown);
    cudaGetSymbolAddress((void**)&kvup,   g_kvup);
    cudaGetSymbolAddress((void**)&qup,    g_qup);
    cudaGetSymbolAddress((void**)&qcat,   g_qcat);
    cudaGetSymbolAddress((void**)&kcat,   g_kcat);
    cudaGetSymbolAddress((void**)&vt,     g_vt);
    cudaGetSymbolAddress((void**)&attn,   g_attn);
    cudaGetSymbolAddress((void**)&rc,     g_ropec);
    cudaGetSymbolAddress((void**)&rs,     g_ropes);

    cudaFuncSetAttribute(gemm_f16, cudaFuncAttributeMaxDynamicSharedMemorySize,
                         (int)GH_SMEM);
    cudaFuncSetAttribute(gemm_up_fused, cudaFuncAttributeMaxDynamicSharedMemorySize,
                         (int)GH_SMEM);
    cudaFuncSetAttribute(flash_attn_mma, cudaFuncAttributeMaxDynamicSharedMemorySize,
                         (int)ATTN_SMEM);

    // ---- merged weight transpose+convert (single launch) ----
    {
        TJobs jobs;
        const float* srcs[8] = {W_kv_down, W_q_down, W_k_nope, W_k_rope,
                                W_v, W_q_nope, W_q_rope, W_o};
        __half* dsts[8] = {w_down, w_down, w_kv, w_kv, w_kv, w_q, w_q, w_o};
        int Rs[8]    = {DIM, DIM, KV_RANK, KV_RANK, KV_RANK, Q_RANK, Q_RANK, NH*V_D};
        int Cs[8]    = {KV_RANK, Q_RANK, NKV*NOPE_D, NKV*ROPE_D, NKV*V_D,
                        NH*NOPE_D, NH*ROPE_D, DIM};
        int noffs[8] = {0, KV_RANK, 0, NKV*NOPE_D, VOFF, 0, NH*NOPE_D, 0};
        int cum = 0;
        for (int k = 0; k < 8; k++) {
            jobs.src[k] = srcs[k]; jobs.dst[k] = dsts[k];
            jobs.R[k] = Rs[k]; jobs.C[k] = Cs[k]; jobs.noff[k] = noffs[k];
            jobs.start[k] = cum;
            cum += (Rs[k] / 32) * (Cs[k] / 32);
        }
        jobs.njobs = 8;
        trans_half_multi<<<cum, dim3(32, 8)>>>(jobs);
    }
    prep_misc<<<TBL_B + 592, 256>>>(rc, rs, (__half2*)x_r, (const float4*)x,
                                    MROWS * DIM / 4);

    // ---- fused down projection: [kv_c | q_c] ----
    gemm_f16<<<(N_DOWN/128) * (MROWS/128), 256, GH_SMEM>>>(
        x_r, DIM, w_down, cdown, N_DOWN, DIM, 1);

    // ---- fused up projections (q-up tiles first, kv-up packs the tail) ----
    gemm_up_fused<<<QUP_TILES + KVUP_TILES, 256, GH_SMEM>>>(
        cdown, w_q, w_kv, qup, kvup);

    // ---- fused RoPE assembly + V transpose (single launch, vectorized) ----
    assemble_all<<<NQN + NQR + NKN + NKR + NTV, 256>>>(
        qup, kvup, rc, rs, qcat, kcat, vt);

    // ---- attention (1D grid, largest tiles first) ----
    flash_attn_mma<<<(TT/128) * BB * NH, 256, ATTN_SMEM>>>(qcat, kcat, vt, attn);

    // ---- output projection (float out) ----
    gemm_f16<<<(DIM/128) * (MROWS/128), 256, GH_SMEM>>>(
        attn, NH*V_D, w_o, out, DIM, NH*V_D, 0);
}

// round 17
// speedup vs baseline: 1.1224x; 1.0121x over previous
#include <cuda_runtime.h>
#include <cuda_fp16.h>
#include <math.h>
#include <stdint.h>

// Problem constants
#define BB 2
#define TT 2048
#define DIM 2048
#define NH 16
#define NKV 4
#define NREP 4
#define ROPE_D 64
#define NOPE_D 128
#define V_D 128
#define QK_D 192
#define KV_RANK 512
#define Q_RANK 1536
#define MROWS (BB*TT)   // 4096

// fused widths
#define N_DOWN 2048            // [kv_c(512) | q_c(1536)]
#define N_KVUP 1280            // [k_nope(512) | k_rope(256) | v(512)]
#define N_QUP  3072            // [q_nope(2048) | q_rope(1024)]
#define VOFF   (NKV*NOPE_D + NKV*ROPE_D)   // 768

// ------------------------- scratch (static device memory) -------------------
__device__ __half g_w_down[N_DOWN * DIM];       // transposed [N][K], fp16
__device__ __half g_w_kv  [N_KVUP * KV_RANK];
__device__ __half g_w_q   [N_QUP * Q_RANK];
__device__ __half g_w_o   [DIM * (NH*V_D)];
__device__ __half g_x_r   [MROWS * DIM];
__device__ __half g_cdown [MROWS * N_DOWN];
__device__ __half g_qcat  [BB*NH  * TT * QK_D];
__device__ __half g_kcat  [BB*NKV * TT * QK_D];
__device__ __half g_vt    [BB*NKV * V_D * TT];
__device__ __half g_attn  [MROWS * (NH*V_D)];
__device__ float  g_ropec [TT * ROPE_D];
__device__ float  g_ropes [TT * ROPE_D];

// ------------------------- common PTX helpers -------------------------------
__device__ __forceinline__ uint32_t s2u(const void* p) {
    return (uint32_t)__cvta_generic_to_shared(p);
}
__device__ __forceinline__ void cp_async16(void* smem, const void* gmem) {
    asm volatile("cp.async.cg.shared.global [%0], [%1], 16;\n"
                 :: "r"(s2u(smem)), "l"(gmem));
}
__device__ __forceinline__ void cp_commit() {
    asm volatile("cp.async.commit_group;\n" ::: "memory");
}
template<int N>
__device__ __forceinline__ void cp_wait() {
    asm volatile("cp.async.wait_group %0;\n" :: "n"(N) : "memory");
}

#define LDMX4(r0, r1, r2, r3, addr) \
    asm volatile("ldmatrix.sync.aligned.m8n8.x4.shared.b16 {%0,%1,%2,%3}, [%4];" \
                 : "=r"(r0), "=r"(r1), "=r"(r2), "=r"(r3) : "r"(addr))

#define MMA_F16(c, a, b) \
    asm volatile("mma.sync.aligned.m16n8k16.row.col.f32.f16.f16.f32 " \
                 "{%0,%1,%2,%3},{%4,%5,%6,%7},{%8,%9},{%0,%1,%2,%3};" \
                 : "+f"((c)[0]), "+f"((c)[1]), "+f"((c)[2]), "+f"((c)[3]) \
                 : "r"((a)[0]), "r"((a)[1]), "r"((a)[2]), "r"((a)[3]), \
                   "r"((b)[0]), "r"((b)[1]))

// ------------------------- prep kernels --------------------------------------
// fused: rope table (first TBL_B blocks) + x float->half copy
#define TBL_B ((TT*ROPE_D + 255) / 256)        // 512
__global__ void prep_misc(float* __restrict__ rc, float* __restrict__ rs,
                          __half2* __restrict__ xdst, const float4* __restrict__ xsrc,
                          int total4)
{
    const int bid = blockIdx.x;
    if (bid < TBL_B) {
        int idx = bid * 256 + threadIdx.x;
        int t = idx >> 6, dr = idx & 63;
        int j = dr & 31;
        float theta = exp2f(-0.4152410118609203f * (float)j);  // 10000^(-j/32)
        float ang = (float)t * theta;
        rc[idx] = cosf(ang);
        rs[idx] = sinf(ang);
    } else {
        for (int i = (bid - TBL_B) * 256 + threadIdx.x; i < total4;
             i += (gridDim.x - TBL_B) * 256) {
            float4 v = xsrc[i];
            xdst[2*i]   = __floats2half2_rn(v.x, v.y);
            xdst[2*i+1] = __floats2half2_rn(v.z, v.w);
        }
    }
}

// merged transpose+convert: 8 jobs in one launch
struct TJobs {
    const float* src[8];
    __half* dst[8];
    int R[8], C[8], noff[8], start[8];
    int njobs;
};

__global__ void trans_half_multi(TJobs jobs)
{
    __shared__ float tile[32][33];
    const int bid = blockIdx.x;
    int jj = 0;
    #pragma unroll
    for (int k = 1; k < 8; k++)
        if (k < jobs.njobs && bid >= jobs.start[k]) jj = k;
    const int local = bid - jobs.start[jj];
    const int C = jobs.C[jj], R = jobs.R[jj], noff = jobs.noff[jj];
    const int tx = C >> 5;
    const int c0 = (local % tx) * 32;
    const int r0 = (local / tx) * 32;
    const float* src = jobs.src[jj];
    __half* dst = jobs.dst[jj];

    for (int i = threadIdx.y; i < 32; i += 8)
        tile[i][threadIdx.x] = src[(size_t)(r0 + i) * C + c0 + threadIdx.x];
    __syncthreads();
    for (int i = threadIdx.y; i < 32; i += 8)
        dst[(size_t)(noff + c0 + i) * R + r0 + threadIdx.x] =
            __float2half_rn(tile[threadIdx.x][i]);
}

// ------------------------- fp16 tensor-core GEMM (mma.sync) -----------------
// Plateau config: block 128x128, 8 warps of 64x32, 256 threads,
// 3-stage cp.async ring, 2 CTAs/SM, K-chunk = 32 halfs.
// Epilogue modes: 0 = float C, 1 = half C,
//                 2 = q-up assembled (qcat),  3 = kv-up assembled (kcat/vt).
#define LDH 40                              // half pitch (80 B/row)
#define TSH (128*LDH)                       // halfs per operand per stage
#define GST3 3
#define GH_SMEM (GST3 * 2 * TSH * sizeof(__half))   // 61440 B
#define LDC 136                             // staging pitch (halfs)

__device__ __forceinline__ void gemm_body(
    const __half* __restrict__ A, int lda,
    const __half* __restrict__ Bt,
    void* __restrict__ Cp, int N, int K, int mode,
    int tile, __half* smh)
{
    const int tid  = threadIdx.x;
    const int lane = tid & 31;
    const int wid  = tid >> 5;
    const int nbx = N >> 7;
    const int bx = tile % nbx, by = tile / nbx;

    const int m0 = (wid & 1) * 64;
    const int n0 = (wid >> 1) * 32;

    const int rselA = ((lane >> 3) & 1) * 8 + (lane & 7);
    const int cselA = (lane >> 4) * 8;
    const int rselB = ((lane >> 4) & 1) * 8 + (lane & 7);
    const int cselB = ((lane >> 3) & 1) * 8;

    const int l_row = tid >> 1;
    const int l_col = (tid & 1) * 16;

    const __half* Agb = A  + (size_t)(by * 128 + l_row) * lda + l_col;
    const __half* Bgb = Bt + (size_t)(bx * 128 + l_row) * K   + l_col;

    float acc[4][4][4];
    #pragma unroll
    for (int i = 0; i < 4; i++)
        #pragma unroll
        for (int j = 0; j < 4; j++)
            #pragma unroll
            for (int r = 0; r < 4; r++) acc[i][j][r] = 0.f;

    const int nch = K >> 5;

    #pragma unroll
    for (int p = 0; p < 2; p++) {
        __half* Asb = smh + p * 2 * TSH + l_row * LDH + l_col;
        __half* Bsb = Asb + TSH;
        const __half* Ag = Agb + p * 32;
        const __half* Bg = Bgb + p * 32;
        #pragma unroll
        for (int i = 0; i < 2; i++) cp_async16(Asb + i*8, Ag + i*8);
        #pragma unroll
        for (int i = 0; i < 2; i++) cp_async16(Bsb + i*8, Bg + i*8);
        cp_commit();
    }

    int s = 0, s2 = 2;
    for (int ch = 0; ch < nch; ch++) {
        cp_wait<1>();
        __syncthreads();

        if (ch + 2 < nch) {
            const int k0 = (ch + 2) << 5;
            __half* Asb = smh + s2 * 2 * TSH + l_row * LDH + l_col;
            __half* Bsb = Asb + TSH;
            const __half* Ag = Agb + k0;
            const __half* Bg = Bgb + k0;
            #pragma unroll
            for (int i = 0; i < 2; i++) cp_async16(Asb + i*8, Ag + i*8);
            #pragma unroll
            for (int i = 0; i < 2; i++) cp_async16(Bsb + i*8, Bg + i*8);
        }
        cp_commit();

        const __half* Asb = smh + s * 2 * TSH;
        const __half* Bsb = Asb + TSH;

        #pragma unroll
        for (int kk = 0; kk < 2; kk++) {
            uint32_t af[4][4], bf[4][2];
            #pragma unroll
            for (int mi = 0; mi < 4; mi++) {
                LDMX4(af[mi][0], af[mi][1], af[mi][2], af[mi][3],
                      s2u(Asb + (m0 + mi*16 + rselA) * LDH + kk*16 + cselA));
            }
            #pragma unroll
            for (int nip = 0; nip < 2; nip++) {
                LDMX4(bf[2*nip][0], bf[2*nip][1], bf[2*nip+1][0], bf[2*nip+1][1],
                      s2u(Bsb + (n0 + nip*16 + rselB) * LDH + kk*16 + cselB));
            }
            #pragma unroll
            for (int mi = 0; mi < 4; mi++)
                #pragma unroll
                for (int ni = 0; ni < 4; ni++)
                    MMA_F16(acc[mi][ni], af[mi], bf[ni]);
        }
        s  = (s  == GST3-1) ? 0 : s  + 1;
        s2 = (s2 == GST3-1) ? 0 : s2 + 1;
    }

    const int crow_l = m0 + (lane >> 2);
    const int ccol_l = n0 + (lane & 3) * 2;

    if (mode == 0) {
        float* C = (float*)Cp;
        #pragma unroll
        for (int mi = 0; mi < 4; mi++)
            #pragma unroll
            for (int ni = 0; ni < 4; ni++) {
                const int r = by * 128 + crow_l + mi * 16;
                const int c = bx * 128 + ccol_l + ni * 8;
                *(float2*)(C + (size_t)r * N + c) =
                    make_float2(acc[mi][ni][0], acc[mi][ni][1]);
                *(float2*)(C + (size_t)(r + 8) * N + c) =
                    make_float2(acc[mi][ni][2], acc[mi][ni][3]);
            }
        return;
    }
    if (mode == 1) {
        __half* C = (__half*)Cp;
        #pragma unroll
        for (int mi = 0; mi < 4; mi++)
            #pragma unroll
            for (int ni = 0; ni < 4; ni++) {
                const int r = by * 128 + crow_l + mi * 16;
                const int c = bx * 128 + ccol_l + ni * 8;
                *(__half2*)(C + (size_t)r * N + c) =
                    __floats2half2_rn(acc[mi][ni][0], acc[mi][ni][1]);
                *(__half2*)(C + (size_t)(r + 8) * N + c) =
                    __floats2half2_rn(acc[mi][ni][2], acc[mi][ni][3]);
            }
        return;
    }

    const float scale = rsqrtf((float)QK_D);

    // mode 2: q-up.  bx<16 -> nope (direct), else rope (staged).
    // mode 3: kv-up. bx<4 -> k-nope (direct), bx 4..5 k-rope, bx 6..9 v-T.
    const bool direct = (mode == 2) ? (bx < 16) : (bx < 4);
    if (direct) {
        const int h = bx;
        const float scl = (mode == 2) ? scale : 1.f;
        __half* dst0 = (mode == 2) ? g_qcat : g_kcat;
        const int nhh = (mode == 2) ? NH : NKV;
        #pragma unroll
        for (int mi = 0; mi < 4; mi++)
            #pragma unroll
            for (int ni = 0; ni < 4; ni++) {
                const int rl = crow_l + mi * 16;
                const int cl = ccol_l + ni * 8;
                #pragma unroll
                for (int hh = 0; hh < 2; hh++) {
                    const int R = by * 128 + rl + hh * 8;
                    const int b = R >> 11, t = R & 2047;
                    *(__half2*)(dst0 + ((size_t)(b * nhh + h) * TT + t) * QK_D + cl)
                        = __floats2half2_rn(acc[mi][ni][2*hh] * scl,
                                            acc[mi][ni][2*hh+1] * scl);
                }
            }
        return;
    }

    // staged epilogue: park tile in smem
    __syncthreads();
    __half* sC = smh;
    #pragma unroll
    for (int mi = 0; mi < 4; mi++)
        #pragma unroll
        for (int ni = 0; ni < 4; ni++) {
            const int rl = crow_l + mi * 16;
            const int cl = ccol_l + ni * 8;
            *(__half2*)(sC + rl * LDC + cl) =
                __floats2half2_rn(acc[mi][ni][0], acc[mi][ni][1]);
            *(__half2*)(sC + (rl + 8) * LDC + cl) =
                __floats2half2_rn(acc[mi][ni][2], acc[mi][ni][3]);
        }
    __syncthreads();

    const bool is_rope = (mode == 2) || (bx < 6);
    if (is_rope) {
        const int r_l = tid >> 1, p = tid & 1;
        const int R = by * 128 + r_l;
        const int b = R >> 11, t = R & 2047;
        const int h = (mode == 2) ? 2 * (bx - 16) + p : 2 * (bx - 4) + p;
        const float scl = (mode == 2) ? scale : 1.f;
        const __half* src = sC + r_l * LDC + p * 64;
        __half* dst = ((mode == 2)
            ? g_qcat + ((size_t)(b * NH  + h) * TT + t) * QK_D
            : g_kcat + ((size_t)(b * NKV + h) * TT + t) * QK_D) + NOPE_D;
        const float* rcp = g_ropec + t * ROPE_D;
        const float* rsp = g_ropes + t * ROPE_D;
        #pragma unroll
        for (int dr0 = 0; dr0 < 64; dr0 += 8) {
            const int pr0 = (dr0 < 32) ? dr0 + 32 : dr0 - 32;
            const float sgn = (dr0 < 32) ? -1.f : 1.f;
            __half out8[8];
            #pragma unroll
            for (int i = 0; i < 8; i++) {
                float val = __half2float(src[dr0 + i]) * rcp[dr0 + i]
                          + sgn * __half2float(src[pr0 + i]) * rsp[dr0 + i];
                out8[i] = __float2half_rn(val * scl);
            }
            *(uint4*)(dst + dr0) = *(uint4*)out8;
        }
    } else {
        // v transpose: vt[(b*512 + (bx-6)*128 + d)*TT + t]
        const int d_l = tid >> 1, tp = tid & 1;
        const int b = by >> 4;
        const int t0 = (by & 15) * 128 + tp * 64;
        __half out[64];
        #pragma unroll
        for (int i = 0; i < 64; i++)
            out[i] = sC[(tp * 64 + i) * LDC + d_l];
        __half* dst = g_vt + ((size_t)(b * 512 + (bx - 6) * 128 + d_l)) * TT + t0;
        #pragma unroll
        for (int j = 0; j < 8; j++)
            ((uint4*)dst)[j] = ((uint4*)out)[j];
    }
}

__global__ __launch_bounds__(256, 2) void gemm_f16(
    const __half* __restrict__ A, int lda,
    const __half* __restrict__ Bt,
    void* __restrict__ Cp, int N, int K, int mode)
{
    extern __shared__ __half smh[];
    gemm_body(A, lda, Bt, Cp, N, K, mode, blockIdx.x, smh);
}

// fused up-projections with assembled epilogues
#define QUP_TILES ((MROWS/128) * (N_QUP/128))    // 768
#define KVUP_TILES ((MROWS/128) * (N_KVUP/128))  // 320

__global__ __launch_bounds__(256, 2) void gemm_up_fused(
    const __half* __restrict__ cdown,
    const __half* __restrict__ w_q,
    const __half* __restrict__ w_kv)
{
    extern __shared__ __half smh[];
    const int bid = blockIdx.x;
    if (bid < QUP_TILES) {
        gemm_body(cdown + KV_RANK, N_DOWN, w_q, nullptr, N_QUP, Q_RANK, 2,
                  bid, smh);
    } else {
        gemm_body(cdown, N_DOWN, w_kv, nullptr, N_KVUP, KV_RANK, 3,
                  bid - QUP_TILES, smh);
    }
}

// ------------------------- flash attention (fp16 mma, K-tile 64) ------------
#define LQH 200
#define LKH 200
#define LVTH 72
#define LPH 72
#define QS_SZ (128*LQH)
#define KS_SZ (64*LKH)
#define VTS_SZ (128*LVTH)
#define PS_SZ (128*LPH)
#define ATTN_SMEM ((QS_SZ + KS_SZ + VTS_SZ + PS_SZ) * sizeof(__half))

__global__ __launch_bounds__(256) void flash_attn_mma(
    const __half* __restrict__ q, const __half* __restrict__ k,
    const __half* __restrict__ vt, __half* __restrict__ out)
{
    extern __shared__ __half sh[];
    __half* Qs  = sh;
    __half* Ks  = sh + QS_SZ;
    __half* Vts = Ks + KS_SZ;
    __half* Ps  = Vts + VTS_SZ;

    const int bid  = blockIdx.x;
    const int qi   = (TT/128 - 1) - (bid >> 5);
    const int head = bid & 31;
    const int b = head / NH, h = head % NH;
    const int hkv = h / NREP;
    const int tid = threadIdx.x;
    const int lane = tid & 31, wid = tid >> 5;
    const int r = lane >> 2, t = lane & 3;
    const int qw = wid * 16;
    const int qrow0 = qi * 128;

    const int rselA = ((lane >> 3) & 1) * 8 + (lane & 7);
    const int cselA = (lane >> 4) * 8;
    const int rselB = ((lane >> 4) & 1) * 8 + (lane & 7);
    const int cselB = ((lane >> 3) & 1) * 8;

    const __half* qbase = q + ((size_t)head * TT + qrow0) * QK_D;
    const __half* kbase = k + ((size_t)(b * NKV + hkv) * TT) * QK_D;
    const __half* vtbase = vt + (size_t)(b * 512 + hkv * 128) * TT;

    for (int i = tid; i < 128 * 24; i += 256) {
        int rr = i / 24, c8 = i % 24;
        cp_async16(Qs + rr * LQH + c8 * 8, qbase + (size_t)rr * QK_D + c8 * 8);
    }
    cp_commit();
    for (int i = tid; i < 64 * 24; i += 256) {
        int rr = i / 24, c8 = i % 24;
        cp_async16(Ks + rr * LKH + c8 * 8, kbase + (size_t)rr * QK_D + c8 * 8);
    }
    cp_commit();
    for (int i = tid; i < 128 * 8; i += 256) {
        int rr = i >> 3, c8 = i & 7;
        cp_async16(Vts + rr * LVTH + c8 * 8, vtbase + (size_t)rr * TT + c8 * 8);
    }
    cp_commit();

    float m0 = -1e30f, m1 = -1e30f, l0 = 0.f, l1 = 0.f;
    float oacc[16][4];
    #pragma unroll
    for (int j = 0; j < 16; j++)
        #pragma unroll
        for (int c = 0; c < 4; c++) oacc[j][c] = 0.f;

    const int niter = 2 * qi + 2;
    for (int jt = 0; jt < niter; jt++) {
        const int krow0 = jt * 64;

        cp_wait<1>();
        __syncthreads();

        float sacc[8][4];
        #pragma unroll
        for (int j = 0; j < 8; j++)
            #pragma unroll
            for (int c = 0; c < 4; c++) sacc[j][c] = 0.f;

        #pragma unroll 2
        for (int kc = 0; kc < 12; kc++) {
            uint32_t a[4];
            LDMX4(a[0], a[1], a[2], a[3],
                  s2u(Qs + (qw + rselA) * LQH + kc*16 + cselA));
            #pragma unroll
            for (int jp = 0; jp < 4; jp++) {
                uint32_t b0[2], b1[2];
                LDMX4(b0[0], b0[1], b1[0], b1[1],
                      s2u(Ks + (jp*16 + rselB) * LKH + kc*16 + cselB));
                MMA_F16(sacc[2*jp],   a, b0);
                MMA_F16(sacc[2*jp+1], a, b1);
            }
        }

        const int gr0 = qrow0 + qw + r;
        const bool need_mask = (jt >= 2 * qi);
        float mx0 = m0, mx1 = m1;
        #pragma unroll
        for (int j = 0; j < 8; j++) {
            if (need_mask) {
                int gc = krow0 + 8 * j + 2 * t;
                if (gc     > gr0)     sacc[j][0] = -1e30f;
                if (gc + 1 > gr0)     sacc[j][1] = -1e30f;
                if (gc     > gr0 + 8) sacc[j][2] = -1e30f;
                if (gc + 1 > gr0 + 8) sacc[j][3] = -1e30f;
            }
            mx0 = fmaxf(mx0, fmaxf(sacc[j][0], sacc[j][1]));
            mx1 = fmaxf(mx1, fmaxf(sacc[j][2], sacc[j][3]));
        }
        mx0 = fmaxf(mx0, __shfl_xor_sync(0xffffffffu, mx0, 1));
        mx0 = fmaxf(mx0, __shfl_xor_sync(0xffffffffu, mx0, 2));
        mx1 = fmaxf(mx1, __shfl_xor_sync(0xffffffffu, mx1, 1));
        mx1 = fmaxf(mx1, __shfl_xor_sync(0xffffffffu, mx1, 2));

        float alpha0 = __expf(m0 - mx0);
        float alpha1 = __expf(m1 - mx1);
        m0 = mx0; m1 = mx1;

        float ls0 = 0.f, ls1 = 0.f;
        __half2* pp = (__half2*)(Ps + (qw + r) * LPH);
        #pragma unroll
        for (int j = 0; j < 8; j++) {
            float p0 = __expf(sacc[j][0] - mx0);
            float p1 = __expf(sacc[j][1] - mx0);
            float p2 = __expf(sacc[j][2] - mx1);
            float p3 = __expf(sacc[j][3] - mx1);
            ls0 += p0 + p1; ls1 += p2 + p3;
            pp[4*j + t]                = __floats2half2_rn(p0, p1);
            pp[8*(LPH/2) + 4*j + t]    = __floats2half2_rn(p2, p3);
        }
        ls0 += __shfl_xor_sync(0xffffffffu, ls0, 1);
        ls0 += __shfl_xor_sync(0xffffffffu, ls0, 2);
        ls1 += __shfl_xor_sync(0xffffffffu, ls1, 1);
        ls1 += __shfl_xor_sync(0xffffffffu, ls1, 2);
        l0 = l0 * alpha0 + ls0;
        l1 = l1 * alpha1 + ls1;

        #pragma unroll
        for (int j = 0; j < 16; j++) {
            oacc[j][0] *= alpha0; oacc[j][1] *= alpha0;
            oacc[j][2] *= alpha1; oacc[j][3] *= alpha1;
        }

        cp_wait<0>();
        __syncthreads();

        if (jt + 1 < niter) {
            const int kn0 = (jt + 1) * 64;
            for (int i = tid; i < 64 * 24; i += 256) {
                int rr = i / 24, c8 = i % 24;
                cp_async16(Ks + rr * LKH + c8 * 8,
                           kbase + (size_t)(kn0 + rr) * QK_D + c8 * 8);
            }
            cp_commit();
        }

        #pragma unroll
        for (int kc = 0; kc < 4; kc++) {
            uint32_t a[4];
            LDMX4(a[0], a[1], a[2], a[3],
                  s2u(Ps + (qw + rselA) * LPH + kc*16 + cselA));
            #pragma unroll
            for (int jp = 0; jp < 8; jp++) {
                uint32_t b0[2], b1[2];
                LDMX4(b0[0], b0[1], b1[0], b1[1],
                      s2u(Vts + (jp*16 + rselB) * LVTH + kc*16 + cselB));
                MMA_F16(oacc[2*jp],   a, b0);
                MMA_F16(oacc[2*jp+1], a, b1);
            }
        }
        __syncthreads();

        if (jt + 1 < niter) {
            const int kn0 = (jt + 1) * 64;
            for (int i = tid; i < 128 * 8; i += 256) {
                int rr = i >> 3, c8 = i & 7;
                cp_async16(Vts + rr * LVTH + c8 * 8,
                           vtbase + (size_t)rr * TT + kn0 + c8 * 8);
            }
            cp_commit();
        }
    }

    const float inv0 = 1.0f / l0;
    const float inv1 = 1.0f / l1;
    const int gr0 = qrow0 + qw + r;
    __half* ob = out + ((size_t)b * TT + gr0) * (NH * V_D) + h * V_D;
    #pragma unroll
    for (int j = 0; j < 16; j++) {
        int c = 8 * j + 2 * t;
        *(__half2*)(ob + c) =
            __floats2half2_rn(oacc[j][0] * inv0, oacc[j][1] * inv0);
        *(__half2*)(ob + (size_t)8 * (NH * V_D) + c) =
            __floats2half2_rn(oacc[j][2] * inv1, oacc[j][3] * inv1);
    }
}

// ------------------------- launch -------------------------------------------
extern "C" void kernel_launch(void* const* d_in, const int* in_sizes, int n_in,
                              void* d_out, int out_size)
{
    const float* x         = (const float*)d_in[0];
    const float* W_kv_down = (const float*)d_in[1];
    const float* W_k_nope  = (const float*)d_in[2];
    const float* W_k_rope  = (const float*)d_in[3];
    const float* W_v       = (const float*)d_in[4];
    const float* W_q_down  = (const float*)d_in[5];
    const float* W_q_nope  = (const float*)d_in[6];
    const float* W_q_rope  = (const float*)d_in[7];
    const float* W_o       = (const float*)d_in[8];
    float* out = (float*)d_out;

    __half *w_down, *w_kv, *w_q, *w_o, *x_r, *cdown;
    __half *qcat, *kcat, *vt, *attn;
    float *rc, *rs;
    cudaGetSymbolAddress((void**)&w_down, g_w_down);
    cudaGetSymbolAddress((void**)&w_kv,   g_w_kv);
    cudaGetSymbolAddress((void**)&w_q,    g_w_q);
    cudaGetSymbolAddress((void**)&w_o,    g_w_o);
    cudaGetSymbolAddress((void**)&x_r,    g_x_r);
    cudaGetSymbolAddress((void**)&cdown,  g_cdown);
    cudaGetSymbolAddress((void**)&qcat,   g_qcat);
    cudaGetSymbolAddress((void**)&kcat,   g_kcat);
    cudaGetSymbolAddress((void**)&vt,     g_vt);
    cudaGetSymbolAddress((void**)&attn,   g_attn);
    cudaGetSymbolAddress((void**)&rc,     g_ropec);
    cudaGetSymbolAddress((void**)&rs,     g_ropes);

    cudaFuncSetAttribute(gemm_f16, cudaFuncAttributeMaxDynamicSharedMemorySize,
                         (int)GH_SMEM);
    cudaFuncSetAttribute(gemm_up_fused, cudaFuncAttributeMaxDynamicSharedMemorySize,
                         (int)GH_SMEM);
    cudaFuncSetAttribute(flash_attn_mma, cudaFuncAttributeMaxDynamicSharedMemorySize,
                         (int)ATTN_SMEM);

    // ---- merged weight transpose+convert (single launch) ----
    {
        TJobs jobs;
        const float* srcs[8] = {W_kv_down, W_q_down, W_k_nope, W_k_rope,
                                W_v, W_q_nope, W_q_rope, W_o};
        __half* dsts[8] = {w_down, w_down, w_kv, w_kv, w_kv, w_q, w_q, w_o};
        int Rs[8]    = {DIM, DIM, KV_RANK, KV_RANK, KV_RANK, Q_RANK, Q_RANK, NH*V_D};
        int Cs[8]    = {KV_RANK, Q_RANK, NKV*NOPE_D, NKV*ROPE_D, NKV*V_D,
                        NH*NOPE_D, NH*ROPE_D, DIM};
        int noffs[8] = {0, KV_RANK, 0, NKV*NOPE_D, VOFF, 0, NH*NOPE_D, 0};
        int cum = 0;
        for (int k = 0; k < 8; k++) {
            jobs.src[k] = srcs[k]; jobs.dst[k] = dsts[k];
            jobs.R[k] = Rs[k]; jobs.C[k] = Cs[k]; jobs.noff[k] = noffs[k];
            jobs.start[k] = cum;
            cum += (Rs[k] / 32) * (Cs[k] / 32);
        }
        jobs.njobs = 8;
        trans_half_multi<<<cum, dim3(32, 8)>>>(jobs);
    }
    prep_misc<<<TBL_B + 592, 256>>>(rc, rs, (__half2*)x_r, (const float4*)x,
                                    MROWS * DIM / 4);

    // ---- fused down projection: [kv_c | q_c] ----
    gemm_f16<<<(N_DOWN/128) * (MROWS/128), 256, GH_SMEM>>>(
        x_r, DIM, w_down, cdown, N_DOWN, DIM, 1);

    // ---- fused up projections w/ assembled epilogues (qcat/kcat/vt direct) --
    gemm_up_fused<<<QUP_TILES + KVUP_TILES, 256, GH_SMEM>>>(cdown, w_q, w_kv);

    // ---- attention (1D grid, largest tiles first) ----
    flash_attn_mma<<<(TT/128) * BB * NH, 256, ATTN_SMEM>>>(qcat, kcat, vt, attn);

    // ---- output projection (float out) ----
    gemm_f16<<<(DIM/128) * (MROWS/128), 256, GH_SMEM>>>(
        attn, NH*V_D, w_o, out, DIM, NH*V_D, 0);
}